// round 1
// baseline (speedup 1.0000x reference)
#include <cuda_runtime.h>
#include <cstddef>

#define N_NODES 100000
#define N_EDGES 3200000

// ---------------- packed f32x2 helpers ----------------
__device__ __forceinline__ unsigned long long pack2(float a, float b) {
    unsigned long long r;
    asm("mov.b64 %0, {%1, %2};" : "=l"(r) : "f"(a), "f"(b));
    return r;
}
__device__ __forceinline__ void unpack2(unsigned long long v, float& a, float& b) {
    asm("mov.b64 {%0, %1}, %2;" : "=f"(a), "=f"(b) : "l"(v));
}
__device__ __forceinline__ unsigned long long fma2(unsigned long long a,
                                                   unsigned long long b,
                                                   unsigned long long c) {
    unsigned long long d;
    asm("fma.rn.f32x2 %0, %1, %2, %3;" : "=l"(d) : "l"(a), "l"(b), "l"(c));
    return d;
}
__device__ __forceinline__ void relu2(unsigned long long v, float& a, float& b) {
    unpack2(v, a, b);
    a = fmaxf(a, 0.0f);
    b = fmaxf(b, 0.0f);
}

// Accumulate one input row into NPAIR packed accumulators.
// wrow must be 16B-aligned, NPAIR even. Covers NPAIR*2 output floats.
template <int NPAIR>
__device__ __forceinline__ void acc_row(unsigned long long* acc, float v, const float* wrow) {
    unsigned long long ev = pack2(v, v);
#pragma unroll
    for (int k = 0; k < NPAIR / 2; k++) {
        ulonglong2 w = *(reinterpret_cast<const ulonglong2*>(wrow) + k);
        acc[2 * k]     = fma2(ev, w.x, acc[2 * k]);
        acc[2 * k + 1] = fma2(ev, w.y, acc[2 * k + 1]);
    }
}

// Row of 6 outputs (3 pairs), 8B-aligned rows.
__device__ __forceinline__ void acc_row6(unsigned long long* acc, float v, const float* wrow) {
    unsigned long long ev = pack2(v, v);
#pragma unroll
    for (int k = 0; k < 3; k++) {
        unsigned long long w = *reinterpret_cast<const unsigned long long*>(wrow + 2 * k);
        acc[k] = fma2(ev, w, acc[k]);
    }
}

__global__ void __launch_bounds__(128) mpn_edge_kernel(
    const float* __restrict__ x_node, const float* __restrict__ x_edge,
    const int* __restrict__ src, const int* __restrict__ dst,
    const float* __restrict__ We1, const float* __restrict__ be1,
    const float* __restrict__ We2, const float* __restrict__ be2,
    const float* __restrict__ Wn1, const float* __restrict__ bn1,
    const float* __restrict__ Wn2, const float* __restrict__ bn2,
    float* __restrict__ out_nm, float* __restrict__ out_em)
{
    __shared__ __align__(16) float sWe1[70 * 32];
    __shared__ __align__(16) float sWe2[32 * 6];
    __shared__ __align__(16) float sWn1[38 * 64];
    __shared__ __align__(16) float sWn2[64 * 32];
    __shared__ __align__(16) float sbe1[32];
    __shared__ __align__(16) float sbe2[8];
    __shared__ __align__(16) float sbn1[64];
    __shared__ __align__(16) float sbn2[32];

    const int t = threadIdx.x;
    for (int i = t; i < 70 * 32; i += 128) sWe1[i] = We1[i];
    for (int i = t; i < 32 * 6; i += 128)  sWe2[i] = We2[i];
    for (int i = t; i < 38 * 64; i += 128) sWn1[i] = Wn1[i];
    for (int i = t; i < 64 * 32; i += 128) sWn2[i] = Wn2[i];
    if (t < 32) sbe1[t] = be1[t];
    if (t < 8)  sbe2[t] = (t < 6) ? be2[t] : 0.0f;
    if (t < 64) sbn1[t] = bn1[t];
    if (t < 32) sbn2[t] = bn2[t];
    __syncthreads();

    const int e = blockIdx.x * 128 + t;
    if (e >= N_EDGES) return;

    const int s = src[e];
    const int d = dst[e];

    // ---- gather inputs into registers ----
    float xd[32], xs[32], xe[6];
    {
        const float4* pd = reinterpret_cast<const float4*>(x_node + (size_t)d * 32);
        const float4* ps = reinterpret_cast<const float4*>(x_node + (size_t)s * 32);
#pragma unroll
        for (int i = 0; i < 8; i++) {
            float4 v = pd[i];
            xd[4 * i] = v.x; xd[4 * i + 1] = v.y; xd[4 * i + 2] = v.z; xd[4 * i + 3] = v.w;
        }
#pragma unroll
        for (int i = 0; i < 8; i++) {
            float4 v = ps[i];
            xs[4 * i] = v.x; xs[4 * i + 1] = v.y; xs[4 * i + 2] = v.z; xs[4 * i + 3] = v.w;
        }
        const float2* pe = reinterpret_cast<const float2*>(x_edge + (size_t)e * 6);
        float2 e0 = pe[0], e1 = pe[1], e2 = pe[2];
        xe[0] = e0.x; xe[1] = e0.y; xe[2] = e1.x; xe[3] = e1.y; xe[4] = e2.x; xe[5] = e2.y;
    }

    // ---- layer 1: edge_in[70] @ We1[70,32] + be1, ReLU ----
    unsigned long long acc1[16];
#pragma unroll
    for (int j = 0; j < 16; j++)
        acc1[j] = *reinterpret_cast<const unsigned long long*>(sbe1 + 2 * j);
#pragma unroll
    for (int i = 0; i < 32; i++) acc_row<16>(acc1, xd[i], sWe1 + i * 32);
#pragma unroll
    for (int i = 0; i < 32; i++) acc_row<16>(acc1, xs[i], sWe1 + (32 + i) * 32);
#pragma unroll
    for (int i = 0; i < 6; i++)  acc_row<16>(acc1, xe[i], sWe1 + (64 + i) * 32);

    float h1[32];
#pragma unroll
    for (int j = 0; j < 16; j++) relu2(acc1[j], h1[2 * j], h1[2 * j + 1]);

    // ---- layer 2: h1[32] @ We2[32,6] + be2, ReLU -> edge_msg ----
    unsigned long long acc2[3];
#pragma unroll
    for (int j = 0; j < 3; j++)
        acc2[j] = *reinterpret_cast<const unsigned long long*>(sbe2 + 2 * j);
#pragma unroll
    for (int i = 0; i < 32; i++) acc_row6(acc2, h1[i], sWe2 + i * 6);

    float em[6];
#pragma unroll
    for (int j = 0; j < 3; j++) relu2(acc2[j], em[2 * j], em[2 * j + 1]);

    // write edge_msg output [E,6]
    {
        float2* po = reinterpret_cast<float2*>(out_em + (size_t)e * 6);
        po[0] = make_float2(em[0], em[1]);
        po[1] = make_float2(em[2], em[3]);
        po[2] = make_float2(em[4], em[5]);
    }

    // ---- layer 3: node_in[38] = [xd, em] @ Wn1[38,64] + bn1, ReLU ----
    unsigned long long acc3[32];
#pragma unroll
    for (int j = 0; j < 32; j++)
        acc3[j] = *reinterpret_cast<const unsigned long long*>(sbn1 + 2 * j);
#pragma unroll
    for (int i = 0; i < 32; i++) acc_row<32>(acc3, xd[i], sWn1 + i * 64);
#pragma unroll
    for (int i = 0; i < 6; i++)  acc_row<32>(acc3, em[i], sWn1 + (32 + i) * 64);

    float h2[64];
#pragma unroll
    for (int j = 0; j < 32; j++) relu2(acc3[j], h2[2 * j], h2[2 * j + 1]);

    // ---- layer 4: h2[64] @ Wn2[64,32] + bn2, ReLU -> node_msg ----
    unsigned long long acc4[16];
#pragma unroll
    for (int j = 0; j < 16; j++)
        acc4[j] = *reinterpret_cast<const unsigned long long*>(sbn2 + 2 * j);
#pragma unroll
    for (int i = 0; i < 64; i++) acc_row<16>(acc4, h2[i], sWn2 + i * 32);

    float nm[32];
#pragma unroll
    for (int j = 0; j < 16; j++) relu2(acc4[j], nm[2 * j], nm[2 * j + 1]);

    // ---- scatter-sum into out_nm[dst] with vector reductions ----
    float* dp = out_nm + (size_t)d * 32;
#pragma unroll
    for (int k = 0; k < 8; k++) {
        asm volatile("red.global.add.v4.f32 [%0], {%1, %2, %3, %4};"
                     :: "l"(dp + 4 * k),
                        "f"(nm[4 * k]), "f"(nm[4 * k + 1]),
                        "f"(nm[4 * k + 2]), "f"(nm[4 * k + 3])
                     : "memory");
    }
}

extern "C" void kernel_launch(void* const* d_in, const int* in_sizes, int n_in,
                              void* d_out, int out_size) {
    const float* x_node = (const float*)d_in[0];
    const float* x_edge = (const float*)d_in[1];
    const int*   src    = (const int*)d_in[2];
    const int*   dst    = (const int*)d_in[3];
    const float* We1    = (const float*)d_in[4];
    const float* be1    = (const float*)d_in[5];
    const float* We2    = (const float*)d_in[6];
    const float* be2    = (const float*)d_in[7];
    const float* Wn1    = (const float*)d_in[8];
    const float* bn1    = (const float*)d_in[9];
    const float* Wn2    = (const float*)d_in[10];
    const float* bn2    = (const float*)d_in[11];

    float* out    = (float*)d_out;
    float* out_nm = out;                                // [N_NODES, 32]
    float* out_em = out + (size_t)N_NODES * 32;         // [N_EDGES, 6]

    // nm is accumulated with atomics; d_out is poisoned -> zero it first.
    cudaMemsetAsync(out_nm, 0, (size_t)N_NODES * 32 * sizeof(float));

    const int threads = 128;
    const int blocks = (N_EDGES + threads - 1) / threads;
    mpn_edge_kernel<<<blocks, threads>>>(x_node, x_edge, src, dst,
                                         We1, be1, We2, be2,
                                         Wn1, bn1, Wn2, bn2,
                                         out_nm, out_em);
}

// round 5
// speedup vs baseline: 1.8588x; 1.8588x over previous
#include <cuda_runtime.h>
#include <cstddef>

#define N_NODES 100000
#define N_EDGES 3200000

typedef unsigned long long ull;

// Per-node precomputed projections (static device scratch — allowed).
__device__ float g_A[(size_t)N_NODES * 32];  // be1 + x@We1[0:32,:]
__device__ float g_B[(size_t)N_NODES * 32];  // x@We1[32:64,:]
__device__ float g_C[(size_t)N_NODES * 64];  // bn1 + x@Wn1[0:32,:]

// ---------------- packed f32x2 helpers ----------------
__device__ __forceinline__ ull pack2(float a, float b) {
    ull r; asm("mov.b64 %0, {%1, %2};" : "=l"(r) : "f"(a), "f"(b)); return r;
}
__device__ __forceinline__ void unpack2(ull v, float& a, float& b) {
    asm("mov.b64 {%0, %1}, %2;" : "=f"(a), "=f"(b) : "l"(v));
}
__device__ __forceinline__ ull fma2(ull a, ull b, ull c) {
    ull d; asm("fma.rn.f32x2 %0, %1, %2, %3;" : "=l"(d) : "l"(a), "l"(b), "l"(c)); return d;
}
__device__ __forceinline__ ull add2(ull a, ull b) {
    ull d; asm("add.rn.f32x2 %0, %1, %2;" : "=l"(d) : "l"(a), "l"(b)); return d;
}
__device__ __forceinline__ void relu2(ull v, float& a, float& b) {
    unpack2(v, a, b);
    a = fmaxf(a, 0.0f);
    b = fmaxf(b, 0.0f);
}

// ================= precompute kernel: per-node projections =================
__global__ void __launch_bounds__(128) mpn_precompute_kernel(
    const float* __restrict__ x_node,
    const float* __restrict__ We1, const float* __restrict__ be1,
    const float* __restrict__ Wn1, const float* __restrict__ bn1)
{
    __shared__ __align__(16) float sW1[64 * 32];   // We1 rows 0..63
    __shared__ __align__(16) float sWn[32 * 64];   // Wn1 rows 0..31
    __shared__ __align__(16) float sbe1[32];
    __shared__ __align__(16) float sbn1[64];

    const int t = threadIdx.x;
    for (int i = t; i < 64 * 32; i += 128) sW1[i] = We1[i];
    for (int i = t; i < 32 * 64; i += 128) sWn[i] = Wn1[i];
    if (t < 32) sbe1[t] = be1[t];
    if (t < 64) sbn1[t] = bn1[t];
    __syncthreads();

    const int n = blockIdx.x * 128 + t;
    if (n >= N_NODES) return;

    float x[32];
    {
        const float4* px = reinterpret_cast<const float4*>(x_node + (size_t)n * 32);
#pragma unroll
        for (int i = 0; i < 8; i++) {
            float4 v = px[i];
            x[4*i] = v.x; x[4*i+1] = v.y; x[4*i+2] = v.z; x[4*i+3] = v.w;
        }
    }

    ull accA[16], accB[16], accC[32];
#pragma unroll
    for (int j = 0; j < 16; j++) {
        accA[j] = *reinterpret_cast<const ull*>(sbe1 + 2 * j);
        accB[j] = pack2(0.0f, 0.0f);
    }
#pragma unroll
    for (int j = 0; j < 32; j++)
        accC[j] = *reinterpret_cast<const ull*>(sbn1 + 2 * j);

#pragma unroll
    for (int i = 0; i < 32; i++) {
        ull ev = pack2(x[i], x[i]);
        const ulonglong2* wa = reinterpret_cast<const ulonglong2*>(sW1 + i * 32);
        const ulonglong2* wb = reinterpret_cast<const ulonglong2*>(sW1 + (32 + i) * 32);
        const ulonglong2* wc = reinterpret_cast<const ulonglong2*>(sWn + i * 64);
#pragma unroll
        for (int k = 0; k < 8; k++) {
            ulonglong2 w = wa[k];
            accA[2*k]   = fma2(ev, w.x, accA[2*k]);
            accA[2*k+1] = fma2(ev, w.y, accA[2*k+1]);
        }
#pragma unroll
        for (int k = 0; k < 8; k++) {
            ulonglong2 w = wb[k];
            accB[2*k]   = fma2(ev, w.x, accB[2*k]);
            accB[2*k+1] = fma2(ev, w.y, accB[2*k+1]);
        }
#pragma unroll
        for (int k = 0; k < 16; k++) {
            ulonglong2 w = wc[k];
            accC[2*k]   = fma2(ev, w.x, accC[2*k]);
            accC[2*k+1] = fma2(ev, w.y, accC[2*k+1]);
        }
    }

    ulonglong2* pA = reinterpret_cast<ulonglong2*>(g_A + (size_t)n * 32);
    ulonglong2* pB = reinterpret_cast<ulonglong2*>(g_B + (size_t)n * 32);
    ulonglong2* pC = reinterpret_cast<ulonglong2*>(g_C + (size_t)n * 64);
#pragma unroll
    for (int k = 0; k < 8; k++) pA[k] = make_ulonglong2(accA[2*k], accA[2*k+1]);
#pragma unroll
    for (int k = 0; k < 8; k++) pB[k] = make_ulonglong2(accB[2*k], accB[2*k+1]);
#pragma unroll
    for (int k = 0; k < 16; k++) pC[k] = make_ulonglong2(accC[2*k], accC[2*k+1]);
}

// ================= edge kernel: 2 edges per thread =================
__global__ void __launch_bounds__(128, 2) mpn_edge_kernel(
    const float* __restrict__ x_edge,
    const int* __restrict__ src, const int* __restrict__ dst,
    const float* __restrict__ We1, const float* __restrict__ We2,
    const float* __restrict__ be2,
    const float* __restrict__ Wn1, const float* __restrict__ Wn2,
    const float* __restrict__ bn2,
    float* __restrict__ out_nm, float* __restrict__ out_em)
{
    __shared__ __align__(16) float sWe1t[6 * 32];   // We1 rows 64..69
    __shared__ __align__(16) float sWe2[32 * 6];
    __shared__ __align__(16) float sWn1t[6 * 64];   // Wn1 rows 32..37
    __shared__ __align__(16) float sWn2[64 * 32];
    __shared__ __align__(16) float sbe2[8];
    __shared__ __align__(16) float sbn2[32];

    const int t = threadIdx.x;
    for (int i = t; i < 6 * 32; i += 128)  sWe1t[i] = We1[64 * 32 + i];
    for (int i = t; i < 32 * 6; i += 128)  sWe2[i]  = We2[i];
    for (int i = t; i < 6 * 64; i += 128)  sWn1t[i] = Wn1[32 * 64 + i];
    for (int i = t; i < 64 * 32; i += 128) sWn2[i]  = Wn2[i];
    if (t < 8)  sbe2[t] = (t < 6) ? be2[t] : 0.0f;
    if (t < 32) sbn2[t] = bn2[t];
    __syncthreads();

    const int e0 = blockIdx.x * 256 + t;   // N_EDGES % 256 == 0
    const int e1 = e0 + 128;

    const int s0 = src[e0], s1 = src[e1];
    const int d0 = dst[e0], d1 = dst[e1];

    // ---- layer 1: acc1 = A[d] + B[s] + xe @ We1[64:70] ----
    ull acc1[2][16];
    {
        const ulonglong2* pa = reinterpret_cast<const ulonglong2*>(g_A + (size_t)d0 * 32);
        const ulonglong2* pb = reinterpret_cast<const ulonglong2*>(g_B + (size_t)s0 * 32);
#pragma unroll
        for (int k = 0; k < 8; k++) {
            ulonglong2 a = pa[k], b = pb[k];
            acc1[0][2*k]   = add2(a.x, b.x);
            acc1[0][2*k+1] = add2(a.y, b.y);
        }
    }
    {
        const ulonglong2* pa = reinterpret_cast<const ulonglong2*>(g_A + (size_t)d1 * 32);
        const ulonglong2* pb = reinterpret_cast<const ulonglong2*>(g_B + (size_t)s1 * 32);
#pragma unroll
        for (int k = 0; k < 8; k++) {
            ulonglong2 a = pa[k], b = pb[k];
            acc1[1][2*k]   = add2(a.x, b.x);
            acc1[1][2*k+1] = add2(a.y, b.y);
        }
    }

    float xe0[6], xe1[6];
    {
        const float2* p0 = reinterpret_cast<const float2*>(x_edge + (size_t)e0 * 6);
        const float2* p1 = reinterpret_cast<const float2*>(x_edge + (size_t)e1 * 6);
        float2 a = p0[0], b = p0[1], c = p0[2];
        xe0[0]=a.x; xe0[1]=a.y; xe0[2]=b.x; xe0[3]=b.y; xe0[4]=c.x; xe0[5]=c.y;
        a = p1[0]; b = p1[1]; c = p1[2];
        xe1[0]=a.x; xe1[1]=a.y; xe1[2]=b.x; xe1[3]=b.y; xe1[4]=c.x; xe1[5]=c.y;
    }

#pragma unroll
    for (int i = 0; i < 6; i++) {
        ull ev0 = pack2(xe0[i], xe0[i]);
        ull ev1 = pack2(xe1[i], xe1[i]);
        const ulonglong2* w = reinterpret_cast<const ulonglong2*>(sWe1t + i * 32);
#pragma unroll
        for (int k = 0; k < 8; k++) {
            ulonglong2 wp = w[k];
            acc1[0][2*k]   = fma2(ev0, wp.x, acc1[0][2*k]);
            acc1[0][2*k+1] = fma2(ev0, wp.y, acc1[0][2*k+1]);
            acc1[1][2*k]   = fma2(ev1, wp.x, acc1[1][2*k]);
            acc1[1][2*k+1] = fma2(ev1, wp.y, acc1[1][2*k+1]);
        }
    }

    float h10[32], h11[32];
#pragma unroll
    for (int j = 0; j < 16; j++) {
        relu2(acc1[0][j], h10[2*j], h10[2*j+1]);
        relu2(acc1[1][j], h11[2*j], h11[2*j+1]);
    }

    // ---- layer 2: em = relu(h1 @ We2 + be2) ----
    ull acc2[2][3];
#pragma unroll
    for (int j = 0; j < 3; j++) {
        ull b = *reinterpret_cast<const ull*>(sbe2 + 2 * j);
        acc2[0][j] = b; acc2[1][j] = b;
    }
#pragma unroll
    for (int i = 0; i < 32; i++) {
        const ull* w = reinterpret_cast<const ull*>(sWe2 + i * 6);
        ull w0 = w[0], w1 = w[1], w2 = w[2];
        ull ev0 = pack2(h10[i], h10[i]);
        ull ev1 = pack2(h11[i], h11[i]);
        acc2[0][0] = fma2(ev0, w0, acc2[0][0]);
        acc2[0][1] = fma2(ev0, w1, acc2[0][1]);
        acc2[0][2] = fma2(ev0, w2, acc2[0][2]);
        acc2[1][0] = fma2(ev1, w0, acc2[1][0]);
        acc2[1][1] = fma2(ev1, w1, acc2[1][1]);
        acc2[1][2] = fma2(ev1, w2, acc2[1][2]);
    }

    float em0[6], em1[6];
#pragma unroll
    for (int j = 0; j < 3; j++) {
        relu2(acc2[0][j], em0[2*j], em0[2*j+1]);
        relu2(acc2[1][j], em1[2*j], em1[2*j+1]);
    }
    {
        float2* p0 = reinterpret_cast<float2*>(out_em + (size_t)e0 * 6);
        float2* p1 = reinterpret_cast<float2*>(out_em + (size_t)e1 * 6);
        p0[0] = make_float2(em0[0], em0[1]);
        p0[1] = make_float2(em0[2], em0[3]);
        p0[2] = make_float2(em0[4], em0[5]);
        p1[0] = make_float2(em1[0], em1[1]);
        p1[1] = make_float2(em1[2], em1[3]);
        p1[2] = make_float2(em1[4], em1[5]);
    }

    // ---- layer 3: acc3 = C[d] + em @ Wn1[32:38] ----
    ull acc3[2][32];
    {
        const ulonglong2* pc = reinterpret_cast<const ulonglong2*>(g_C + (size_t)d0 * 64);
#pragma unroll
        for (int k = 0; k < 16; k++) {
            ulonglong2 c = pc[k];
            acc3[0][2*k] = c.x; acc3[0][2*k+1] = c.y;
        }
    }
    {
        const ulonglong2* pc = reinterpret_cast<const ulonglong2*>(g_C + (size_t)d1 * 64);
#pragma unroll
        for (int k = 0; k < 16; k++) {
            ulonglong2 c = pc[k];
            acc3[1][2*k] = c.x; acc3[1][2*k+1] = c.y;
        }
    }
#pragma unroll
    for (int i = 0; i < 6; i++) {
        ull ev0 = pack2(em0[i], em0[i]);
        ull ev1 = pack2(em1[i], em1[i]);
        const ulonglong2* w = reinterpret_cast<const ulonglong2*>(sWn1t + i * 64);
#pragma unroll
        for (int k = 0; k < 16; k++) {
            ulonglong2 wp = w[k];
            acc3[0][2*k]   = fma2(ev0, wp.x, acc3[0][2*k]);
            acc3[0][2*k+1] = fma2(ev0, wp.y, acc3[0][2*k+1]);
            acc3[1][2*k]   = fma2(ev1, wp.x, acc3[1][2*k]);
            acc3[1][2*k+1] = fma2(ev1, wp.y, acc3[1][2*k+1]);
        }
    }

    // ---- layer 4: nm = relu(relu(acc3) @ Wn2 + bn2), fused h2 consumption ----
    ull acc4[2][16];
#pragma unroll
    for (int j = 0; j < 16; j++) {
        ull b = *reinterpret_cast<const ull*>(sbn2 + 2 * j);
        acc4[0][j] = b; acc4[1][j] = b;
    }
#pragma unroll
    for (int j = 0; j < 32; j++) {
        float v00, v01, v10, v11;
        relu2(acc3[0][j], v00, v01);
        relu2(acc3[1][j], v10, v11);
        ull e00 = pack2(v00, v00), e01 = pack2(v01, v01);
        ull e10 = pack2(v10, v10), e11 = pack2(v11, v11);
        // rows 2j and 2j+1 of Wn2 are contiguous (64 floats)
        const ulonglong2* w = reinterpret_cast<const ulonglong2*>(sWn2 + 2 * j * 32);
#pragma unroll
        for (int k = 0; k < 8; k++) {
            ulonglong2 wp = w[k];        // row 2j
            acc4[0][2*k]   = fma2(e00, wp.x, acc4[0][2*k]);
            acc4[0][2*k+1] = fma2(e00, wp.y, acc4[0][2*k+1]);
            acc4[1][2*k]   = fma2(e10, wp.x, acc4[1][2*k]);
            acc4[1][2*k+1] = fma2(e10, wp.y, acc4[1][2*k+1]);
        }
#pragma unroll
        for (int k = 0; k < 8; k++) {
            ulonglong2 wp = w[8 + k];    // row 2j+1
            acc4[0][2*k]   = fma2(e01, wp.x, acc4[0][2*k]);
            acc4[0][2*k+1] = fma2(e01, wp.y, acc4[0][2*k+1]);
            acc4[1][2*k]   = fma2(e11, wp.x, acc4[1][2*k]);
            acc4[1][2*k+1] = fma2(e11, wp.y, acc4[1][2*k+1]);
        }
    }

    // ---- scatter-sum ----
    {
        float nm[32];
#pragma unroll
        for (int j = 0; j < 16; j++) relu2(acc4[0][j], nm[2*j], nm[2*j+1]);
        float* dp = out_nm + (size_t)d0 * 32;
#pragma unroll
        for (int k = 0; k < 8; k++) {
            asm volatile("red.global.add.v4.f32 [%0], {%1, %2, %3, %4};"
                         :: "l"(dp + 4*k), "f"(nm[4*k]), "f"(nm[4*k+1]),
                            "f"(nm[4*k+2]), "f"(nm[4*k+3]) : "memory");
        }
    }
    {
        float nm[32];
#pragma unroll
        for (int j = 0; j < 16; j++) relu2(acc4[1][j], nm[2*j], nm[2*j+1]);
        float* dp = out_nm + (size_t)d1 * 32;
#pragma unroll
        for (int k = 0; k < 8; k++) {
            asm volatile("red.global.add.v4.f32 [%0], {%1, %2, %3, %4};"
                         :: "l"(dp + 4*k), "f"(nm[4*k]), "f"(nm[4*k+1]),
                            "f"(nm[4*k+2]), "f"(nm[4*k+3]) : "memory");
        }
    }
}

extern "C" void kernel_launch(void* const* d_in, const int* in_sizes, int n_in,
                              void* d_out, int out_size) {
    const float* x_node = (const float*)d_in[0];
    const float* x_edge = (const float*)d_in[1];
    const int*   src    = (const int*)d_in[2];
    const int*   dst    = (const int*)d_in[3];
    const float* We1    = (const float*)d_in[4];
    const float* be1    = (const float*)d_in[5];
    const float* We2    = (const float*)d_in[6];
    const float* be2    = (const float*)d_in[7];
    const float* Wn1    = (const float*)d_in[8];
    const float* bn1    = (const float*)d_in[9];
    const float* Wn2    = (const float*)d_in[10];
    const float* bn2    = (const float*)d_in[11];

    float* out    = (float*)d_out;
    float* out_nm = out;                        // [N_NODES, 32]
    float* out_em = out + (size_t)N_NODES * 32; // [N_EDGES, 6]

    cudaMemsetAsync(out_nm, 0, (size_t)N_NODES * 32 * sizeof(float));

    mpn_precompute_kernel<<<(N_NODES + 127) / 128, 128>>>(x_node, We1, be1, Wn1, bn1);

    mpn_edge_kernel<<<N_EDGES / 256, 128>>>(x_edge, src, dst,
                                            We1, We2, be2, Wn1, Wn2, bn2,
                                            out_nm, out_em);
}

// round 7
// speedup vs baseline: 2.1391x; 1.1509x over previous
#include <cuda_runtime.h>
#include <cuda_bf16.h>
#include <cstddef>
#include <cstdint>

#define N_NODES 100000
#define N_EDGES 3200000
#define NITER 8                 // 128-edge tiles per block
#define GRID_EDGE 3125          // 3125 * 8 * 128 = 3,200,000

typedef unsigned long long ull;

// Per-node precomputed projections (static device scratch — allowed).
__device__ float g_A[(size_t)N_NODES * 32];  // be1 + x@We1[0:32,:]
__device__ float g_B[(size_t)N_NODES * 32];  // x@We1[32:64,:]
__device__ float g_C[(size_t)N_NODES * 64];  // bn1 + x@Wn1[0:32,:]

// ---------------- packed f32x2 helpers ----------------
__device__ __forceinline__ ull pack2(float a, float b) {
    ull r; asm("mov.b64 %0, {%1, %2};" : "=l"(r) : "f"(a), "f"(b)); return r;
}
__device__ __forceinline__ void unpack2(ull v, float& a, float& b) {
    asm("mov.b64 {%0, %1}, %2;" : "=f"(a), "=f"(b) : "l"(v));
}
__device__ __forceinline__ ull fma2(ull a, ull b, ull c) {
    ull d; asm("fma.rn.f32x2 %0, %1, %2, %3;" : "=l"(d) : "l"(a), "l"(b), "l"(c)); return d;
}
__device__ __forceinline__ ull add2(ull a, ull b) {
    ull d; asm("add.rn.f32x2 %0, %1, %2;" : "=l"(d) : "l"(a), "l"(b)); return d;
}
__device__ __forceinline__ void relu2(ull v, float& a, float& b) {
    unpack2(v, a, b);
    a = fmaxf(a, 0.0f);
    b = fmaxf(b, 0.0f);
}

__device__ __forceinline__ uint32_t smem_u32(const void* p) {
    uint32_t a;
    asm("{ .reg .u64 tmp; cvta.to.shared.u64 tmp, %1; cvt.u32.u64 %0, tmp; }"
        : "=r"(a) : "l"(p));
    return a;
}

// ---------------- warp MMA helpers (sm_80-era PTX, safe at compute_103) ----
__device__ __forceinline__ void ldsm_x4(uint32_t* r, uint32_t addr) {
    asm volatile("ldmatrix.sync.aligned.m8n8.x4.shared.b16 {%0,%1,%2,%3}, [%4];"
                 : "=r"(r[0]), "=r"(r[1]), "=r"(r[2]), "=r"(r[3]) : "r"(addr));
}
__device__ __forceinline__ void mma_bf16(float* c, const uint32_t* a,
                                         uint32_t b0, uint32_t b1) {
    asm volatile(
        "mma.sync.aligned.m16n8k16.row.col.f32.bf16.bf16.f32 "
        "{%0,%1,%2,%3}, {%4,%5,%6,%7}, {%8,%9}, {%0,%1,%2,%3};"
        : "+f"(c[0]), "+f"(c[1]), "+f"(c[2]), "+f"(c[3])
        : "r"(a[0]), "r"(a[1]), "r"(a[2]), "r"(a[3]), "r"(b0), "r"(b1));
}

// SMEM layout (dynamic). A-plane row stride 144B -> conflict-free ldmatrix.
#define SM_WE1T 0          // 6*32 f32 = 768B
#define SM_WE2  768        // 32*6 f32 = 768B
#define SM_WN1T 1536       // 6*64 f32 = 1536B
#define SM_BE2  3072       // 8 f32
#define SM_BN2  3104       // 32 f32
#define SM_BHI  3328       // Wn2 hi, kpair-major [32][32] b32 = 4096B
#define SM_BLO  7424       // Wn2 lo = 4096B
#define SM_A    11520      // per warp: hi 32x144 + lo 32x144 = 9216B; x4 warps
#define A_STRIDE 144
#define A_WARP  9216
#define SM_TOTAL (11520 + 4 * A_WARP)   // 48384 <= 48KB default

// ================= precompute kernel: per-node projections =================
__global__ void __launch_bounds__(128) mpn_precompute_kernel(
    const float* __restrict__ x_node,
    const float* __restrict__ We1, const float* __restrict__ be1,
    const float* __restrict__ Wn1, const float* __restrict__ bn1)
{
    __shared__ __align__(16) float sW1[64 * 32];
    __shared__ __align__(16) float sWn[32 * 64];
    __shared__ __align__(16) float sbe1[32];
    __shared__ __align__(16) float sbn1[64];

    const int t = threadIdx.x;
    for (int i = t; i < 64 * 32; i += 128) sW1[i] = We1[i];
    for (int i = t; i < 32 * 64; i += 128) sWn[i] = Wn1[i];
    if (t < 32) sbe1[t] = be1[t];
    if (t < 64) sbn1[t] = bn1[t];
    __syncthreads();

    const int n = blockIdx.x * 128 + t;
    if (n >= N_NODES) return;

    float x[32];
    {
        const float4* px = reinterpret_cast<const float4*>(x_node + (size_t)n * 32);
#pragma unroll
        for (int i = 0; i < 8; i++) {
            float4 v = px[i];
            x[4*i] = v.x; x[4*i+1] = v.y; x[4*i+2] = v.z; x[4*i+3] = v.w;
        }
    }

    ull accA[16], accB[16], accC[32];
#pragma unroll
    for (int j = 0; j < 16; j++) {
        accA[j] = *reinterpret_cast<const ull*>(sbe1 + 2 * j);
        accB[j] = pack2(0.0f, 0.0f);
    }
#pragma unroll
    for (int j = 0; j < 32; j++)
        accC[j] = *reinterpret_cast<const ull*>(sbn1 + 2 * j);

#pragma unroll
    for (int i = 0; i < 32; i++) {
        ull ev = pack2(x[i], x[i]);
        const ulonglong2* wa = reinterpret_cast<const ulonglong2*>(sW1 + i * 32);
        const ulonglong2* wb = reinterpret_cast<const ulonglong2*>(sW1 + (32 + i) * 32);
        const ulonglong2* wc = reinterpret_cast<const ulonglong2*>(sWn + i * 64);
#pragma unroll
        for (int k = 0; k < 8; k++) {
            ulonglong2 w = wa[k];
            accA[2*k]   = fma2(ev, w.x, accA[2*k]);
            accA[2*k+1] = fma2(ev, w.y, accA[2*k+1]);
        }
#pragma unroll
        for (int k = 0; k < 8; k++) {
            ulonglong2 w = wb[k];
            accB[2*k]   = fma2(ev, w.x, accB[2*k]);
            accB[2*k+1] = fma2(ev, w.y, accB[2*k+1]);
        }
#pragma unroll
        for (int k = 0; k < 16; k++) {
            ulonglong2 w = wc[k];
            accC[2*k]   = fma2(ev, w.x, accC[2*k]);
            accC[2*k+1] = fma2(ev, w.y, accC[2*k+1]);
        }
    }

    ulonglong2* pA = reinterpret_cast<ulonglong2*>(g_A + (size_t)n * 32);
    ulonglong2* pB = reinterpret_cast<ulonglong2*>(g_B + (size_t)n * 32);
    ulonglong2* pC = reinterpret_cast<ulonglong2*>(g_C + (size_t)n * 64);
#pragma unroll
    for (int k = 0; k < 8; k++) pA[k] = make_ulonglong2(accA[2*k], accA[2*k+1]);
#pragma unroll
    for (int k = 0; k < 8; k++) pB[k] = make_ulonglong2(accB[2*k], accB[2*k+1]);
#pragma unroll
    for (int k = 0; k < 16; k++) pC[k] = make_ulonglong2(accC[2*k], accC[2*k+1]);
}

// ======= edge kernel: layers 1-3 f32x2, layer 4 warp mma.sync bf16 =========
__global__ void __launch_bounds__(128) mpn_edge_kernel(
    const float* __restrict__ x_edge,
    const int* __restrict__ src, const int* __restrict__ dst,
    const float* __restrict__ We1, const float* __restrict__ We2,
    const float* __restrict__ be2,
    const float* __restrict__ Wn1, const float* __restrict__ Wn2,
    const float* __restrict__ bn2,
    float* __restrict__ out_nm, float* __restrict__ out_em)
{
    extern __shared__ char smem[];
    const uint32_t smem_base = smem_u32(smem);
    const int t = threadIdx.x;
    const int wid = t >> 5;
    const int lane = t & 31;

    float* sWe1t = reinterpret_cast<float*>(smem + SM_WE1T);
    float* sWe2  = reinterpret_cast<float*>(smem + SM_WE2);
    float* sWn1t = reinterpret_cast<float*>(smem + SM_WN1T);
    float* sbe2  = reinterpret_cast<float*>(smem + SM_BE2);
    uint32_t* sBhi = reinterpret_cast<uint32_t*>(smem + SM_BHI);
    uint32_t* sBlo = reinterpret_cast<uint32_t*>(smem + SM_BLO);

    // ---- stage small weights ----
    for (int i = t; i < 6 * 32; i += 128)  sWe1t[i] = We1[64 * 32 + i];
    for (int i = t; i < 32 * 6; i += 128)  sWe2[i]  = We2[i];
    for (int i = t; i < 6 * 64; i += 128)  sWn1t[i] = Wn1[32 * 64 + i];
    if (t < 8)  sbe2[t] = (t < 6) ? be2[t] : 0.0f;

    // ---- pack Wn2 as bf16 hi/lo, kpair-major: sB[kp*32+n] = {W[2kp][n], W[2kp+1][n]} ----
    for (int i = t; i < 32 * 32; i += 128) {
        int kp = i >> 5, n = i & 31;
        float w0 = Wn2[(2 * kp) * 32 + n];
        float w1 = Wn2[(2 * kp + 1) * 32 + n];
        uint32_t u0 = __float_as_uint(w0), u1 = __float_as_uint(w1);
        sBhi[i] = __byte_perm(u0, u1, 0x7632);   // low16 = w0.hi, high16 = w1.hi
        float l0 = w0 - __uint_as_float(u0 & 0xFFFF0000u);
        float l1 = w1 - __uint_as_float(u1 & 0xFFFF0000u);
        uint32_t lp;
        asm("cvt.rn.bf16x2.f32 %0, %1, %2;" : "=r"(lp) : "f"(l1), "f"(l0));
        sBlo[i] = lp;
    }
    __syncthreads();

    // per-thread epilogue bias pairs: cols nt*8 + (lane&3)*2, +1
    float2 bias[4];
    {
        const float2* b2 = reinterpret_cast<const float2*>(bn2);
#pragma unroll
        for (int nt = 0; nt < 4; nt++) bias[nt] = b2[nt * 4 + (lane & 3)];
    }

    const uint32_t a_hi_base = smem_base + SM_A + wid * A_WARP;
    const uint32_t a_lo_base = a_hi_base + 32 * A_STRIDE;
    // ldmatrix lane address offset within a tile
    const uint32_t lds_lane_off = (uint32_t)(lane & 15) * A_STRIDE + (uint32_t)(lane >> 4) * 16;

    for (int it = 0; it < NITER; it++) {
        const int e = (blockIdx.x * NITER + it) * 128 + t;
        const int s = src[e];
        const int d = dst[e];

        // ---- layer 1: acc1 = A[d] + B[s] + xe @ We1[64:70] ----
        ull acc1[16];
        {
            const ulonglong2* pa = reinterpret_cast<const ulonglong2*>(g_A + (size_t)d * 32);
            const ulonglong2* pb = reinterpret_cast<const ulonglong2*>(g_B + (size_t)s * 32);
#pragma unroll
            for (int k = 0; k < 8; k++) {
                ulonglong2 a = pa[k], b = pb[k];
                acc1[2*k]   = add2(a.x, b.x);
                acc1[2*k+1] = add2(a.y, b.y);
            }
        }
        float xe[6];
        {
            const float2* pe = reinterpret_cast<const float2*>(x_edge + (size_t)e * 6);
            float2 a = pe[0], b = pe[1], c = pe[2];
            xe[0]=a.x; xe[1]=a.y; xe[2]=b.x; xe[3]=b.y; xe[4]=c.x; xe[5]=c.y;
        }
#pragma unroll
        for (int i = 0; i < 6; i++) {
            ull ev = pack2(xe[i], xe[i]);
            const ulonglong2* w = reinterpret_cast<const ulonglong2*>(sWe1t + i * 32);
#pragma unroll
            for (int k = 0; k < 8; k++) {
                ulonglong2 wp = w[k];
                acc1[2*k]   = fma2(ev, wp.x, acc1[2*k]);
                acc1[2*k+1] = fma2(ev, wp.y, acc1[2*k+1]);
            }
        }
        float h1[32];
#pragma unroll
        for (int j = 0; j < 16; j++) relu2(acc1[j], h1[2*j], h1[2*j+1]);

        // ---- layer 2: em = relu(h1 @ We2 + be2) ----
        ull acc2[3];
#pragma unroll
        for (int j = 0; j < 3; j++) acc2[j] = *reinterpret_cast<const ull*>(sbe2 + 2 * j);
#pragma unroll
        for (int i = 0; i < 32; i++) {
            const ull* w = reinterpret_cast<const ull*>(sWe2 + i * 6);
            ull ev = pack2(h1[i], h1[i]);
            acc2[0] = fma2(ev, w[0], acc2[0]);
            acc2[1] = fma2(ev, w[1], acc2[1]);
            acc2[2] = fma2(ev, w[2], acc2[2]);
        }
        float em[6];
#pragma unroll
        for (int j = 0; j < 3; j++) relu2(acc2[j], em[2*j], em[2*j+1]);
        {
            float2* po = reinterpret_cast<float2*>(out_em + (size_t)e * 6);
            po[0] = make_float2(em[0], em[1]);
            po[1] = make_float2(em[2], em[3]);
            po[2] = make_float2(em[4], em[5]);
        }

        // ---- layer 3 (chunked): h2 = relu(C[d] + em @ Wn1[32:38]); bf16 hi/lo ----
        uint32_t ahi[32], alo[32];
        ull emv[6];
#pragma unroll
        for (int i = 0; i < 6; i++) emv[i] = pack2(em[i], em[i]);

#pragma unroll
        for (int c = 0; c < 4; c++) {
            ull acc3[8];
            const ulonglong2* pc = reinterpret_cast<const ulonglong2*>(g_C + (size_t)d * 64 + c * 16);
#pragma unroll
            for (int k = 0; k < 4; k++) {
                ulonglong2 v = pc[k];
                acc3[2*k] = v.x; acc3[2*k+1] = v.y;
            }
#pragma unroll
            for (int i = 0; i < 6; i++) {
                const ulonglong2* w = reinterpret_cast<const ulonglong2*>(sWn1t + i * 64 + c * 16);
#pragma unroll
                for (int k = 0; k < 4; k++) {
                    ulonglong2 wp = w[k];
                    acc3[2*k]   = fma2(emv[i], wp.x, acc3[2*k]);
                    acc3[2*k+1] = fma2(emv[i], wp.y, acc3[2*k+1]);
                }
            }
#pragma unroll
            for (int j = 0; j < 8; j++) {
                float a, b;
                relu2(acc3[j], a, b);
                uint32_t ua = __float_as_uint(a);
                uint32_t ub = __float_as_uint(b);
                float la = a - __uint_as_float(ua & 0xFFFF0000u);
                float lb = b - __uint_as_float(ub & 0xFFFF0000u);
                ahi[c * 8 + j] = __byte_perm(ua, ub, 0x7632);   // {b.hi : a.hi}
                uint32_t lp;
                asm("cvt.rn.bf16x2.f32 %0, %1, %2;" : "=r"(lp) : "f"(lb), "f"(la));
                alo[c * 8 + j] = lp;
            }
        }

        // ---- stage h2 hi/lo rows (row = this lane's edge) ----
        {
            uint4* rh = reinterpret_cast<uint4*>(smem + SM_A + wid * A_WARP + lane * A_STRIDE);
            uint4* rl = reinterpret_cast<uint4*>(smem + SM_A + wid * A_WARP + 32 * A_STRIDE + lane * A_STRIDE);
#pragma unroll
            for (int i = 0; i < 8; i++) {
                rh[i] = make_uint4(ahi[4*i], ahi[4*i+1], ahi[4*i+2], ahi[4*i+3]);
                rl[i] = make_uint4(alo[4*i], alo[4*i+1], alo[4*i+2], alo[4*i+3]);
            }
        }
        __syncwarp();

        // ---- layer 4: C[32x32] = Ahi@(Bhi+Blo) + Alo@Bhi via mma.sync ----
        float acc[8][4];   // [mt*4+nt][frag]
#pragma unroll
        for (int f = 0; f < 8; f++) {
            acc[f][0] = 0.0f; acc[f][1] = 0.0f; acc[f][2] = 0.0f; acc[f][3] = 0.0f;
        }

#pragma unroll
        for (int kt = 0; kt < 4; kt++) {
            uint32_t a0[4], a1[4];
            ldsm_x4(a0, a_hi_base + lds_lane_off + kt * 32);                 // mt=0
            ldsm_x4(a1, a_hi_base + lds_lane_off + 16 * A_STRIDE + kt * 32); // mt=1
            const int kprow = kt * 8 + (lane & 3);
            const int col = (lane >> 2);
#pragma unroll
            for (int nt = 0; nt < 4; nt++) {
                uint32_t bh0 = sBhi[kprow * 32 + nt * 8 + col];
                uint32_t bh1 = sBhi[(kprow + 4) * 32 + nt * 8 + col];
                uint32_t bl0 = sBlo[kprow * 32 + nt * 8 + col];
                uint32_t bl1 = sBlo[(kprow + 4) * 32 + nt * 8 + col];
                mma_bf16(acc[nt],     a0, bh0, bh1);
                mma_bf16(acc[nt],     a0, bl0, bl1);
                mma_bf16(acc[4 + nt], a1, bh0, bh1);
                mma_bf16(acc[4 + nt], a1, bl0, bl1);
            }
        }
#pragma unroll
        for (int kt = 0; kt < 4; kt++) {
            uint32_t a0[4], a1[4];
            ldsm_x4(a0, a_lo_base + lds_lane_off + kt * 32);
            ldsm_x4(a1, a_lo_base + lds_lane_off + 16 * A_STRIDE + kt * 32);
            const int kprow = kt * 8 + (lane & 3);
            const int col = (lane >> 2);
#pragma unroll
            for (int nt = 0; nt < 4; nt++) {
                uint32_t bh0 = sBhi[kprow * 32 + nt * 8 + col];
                uint32_t bh1 = sBhi[(kprow + 4) * 32 + nt * 8 + col];
                mma_bf16(acc[nt],     a0, bh0, bh1);
                mma_bf16(acc[4 + nt], a1, bh0, bh1);
            }
        }
        __syncwarp();   // all lanes done reading A planes before next iter's stores

        // ---- epilogue: bias + relu + scatter-add from fragments ----
        const int r = lane >> 2;
        const int cbase = (lane & 3) * 2;
#pragma unroll
        for (int mt = 0; mt < 2; mt++) {
            int d_lo = __shfl_sync(0xFFFFFFFFu, d, mt * 16 + r);
            int d_hi = __shfl_sync(0xFFFFFFFFu, d, mt * 16 + r + 8);
            float* base_lo = out_nm + (size_t)d_lo * 32 + cbase;
            float* base_hi = out_nm + (size_t)d_hi * 32 + cbase;
#pragma unroll
            for (int nt = 0; nt < 4; nt++) {
                const float* a = acc[mt * 4 + nt];
                float v0 = fmaxf(a[0] + bias[nt].x, 0.0f);
                float v1 = fmaxf(a[1] + bias[nt].y, 0.0f);
                float v2 = fmaxf(a[2] + bias[nt].x, 0.0f);
                float v3 = fmaxf(a[3] + bias[nt].y, 0.0f);
                asm volatile("red.global.add.v2.f32 [%0], {%1, %2};"
                             :: "l"(base_lo + nt * 8), "f"(v0), "f"(v1) : "memory");
                asm volatile("red.global.add.v2.f32 [%0], {%1, %2};"
                             :: "l"(base_hi + nt * 8), "f"(v2), "f"(v3) : "memory");
            }
        }
    }
}

extern "C" void kernel_launch(void* const* d_in, const int* in_sizes, int n_in,
                              void* d_out, int out_size) {
    const float* x_node = (const float*)d_in[0];
    const float* x_edge = (const float*)d_in[1];
    const int*   src    = (const int*)d_in[2];
    const int*   dst    = (const int*)d_in[3];
    const float* We1    = (const float*)d_in[4];
    const float* be1    = (const float*)d_in[5];
    const float* We2    = (const float*)d_in[6];
    const float* be2    = (const float*)d_in[7];
    const float* Wn1    = (const float*)d_in[8];
    const float* bn1    = (const float*)d_in[9];
    const float* Wn2    = (const float*)d_in[10];
    const float* bn2    = (const float*)d_in[11];

    float* out    = (float*)d_out;
    float* out_nm = out;                        // [N_NODES, 32]
    float* out_em = out + (size_t)N_NODES * 32; // [N_EDGES, 6]

    cudaMemsetAsync(out_nm, 0, (size_t)N_NODES * 32 * sizeof(float));

    mpn_precompute_kernel<<<(N_NODES + 127) / 128, 128>>>(x_node, We1, be1, Wn1, bn1);

    mpn_edge_kernel<<<GRID_EDGE, 128, SM_TOTAL>>>(x_edge, src, dst,
                                                  We1, We2, be2, Wn1, Wn2, bn2,
                                                  out_nm, out_em);
}

// round 9
// speedup vs baseline: 2.9276x; 1.3686x over previous
#include <cuda_runtime.h>
#include <cuda_bf16.h>
#include <cstddef>
#include <cstdint>

#define N_NODES 100000
#define N_EDGES 3200000
#define NITER 8                 // 128-edge tiles per block
#define GRID_EDGE 3125          // 3125 * 8 * 128 = 3,200,000

typedef unsigned long long ull;

// Per-node precomputed projections (static device scratch — allowed).
__device__ float g_A[(size_t)N_NODES * 32];  // be1 + x@We1[0:32,:]
__device__ float g_B[(size_t)N_NODES * 32];  // x@We1[32:64,:]
__device__ float g_C[(size_t)N_NODES * 64];  // bn1 + x@Wn1[0:32,:]

// ---------------- packed f32x2 helpers ----------------
__device__ __forceinline__ ull pack2(float a, float b) {
    ull r; asm("mov.b64 %0, {%1, %2};" : "=l"(r) : "f"(a), "f"(b)); return r;
}
__device__ __forceinline__ void unpack2(ull v, float& a, float& b) {
    asm("mov.b64 {%0, %1}, %2;" : "=f"(a), "=f"(b) : "l"(v));
}
__device__ __forceinline__ ull fma2(ull a, ull b, ull c) {
    ull d; asm("fma.rn.f32x2 %0, %1, %2, %3;" : "=l"(d) : "l"(a), "l"(b), "l"(c)); return d;
}
__device__ __forceinline__ ull add2(ull a, ull b) {
    ull d; asm("add.rn.f32x2 %0, %1, %2;" : "=l"(d) : "l"(a), "l"(b)); return d;
}
__device__ __forceinline__ void relu2(ull v, float& a, float& b) {
    unpack2(v, a, b);
    a = fmaxf(a, 0.0f);
    b = fmaxf(b, 0.0f);
}

__device__ __forceinline__ uint32_t smem_u32(const void* p) {
    uint32_t a;
    asm("{ .reg .u64 tmp; cvta.to.shared.u64 tmp, %1; cvt.u32.u64 %0, tmp; }"
        : "=r"(a) : "l"(p));
    return a;
}

// ---------------- warp MMA helpers (sm_80-era PTX, safe at compute_103) ----
__device__ __forceinline__ void ldsm_x4(uint32_t* r, uint32_t addr) {
    asm volatile("ldmatrix.sync.aligned.m8n8.x4.shared.b16 {%0,%1,%2,%3}, [%4];"
                 : "=r"(r[0]), "=r"(r[1]), "=r"(r[2]), "=r"(r[3]) : "r"(addr));
}
__device__ __forceinline__ void mma_bf16(float* c, const uint32_t* a,
                                         uint32_t b0, uint32_t b1) {
    asm volatile(
        "mma.sync.aligned.m16n8k16.row.col.f32.bf16.bf16.f32 "
        "{%0,%1,%2,%3}, {%4,%5,%6,%7}, {%8,%9}, {%0,%1,%2,%3};"
        : "+f"(c[0]), "+f"(c[1]), "+f"(c[2]), "+f"(c[3])
        : "r"(a[0]), "r"(a[1]), "r"(a[2]), "r"(a[3]), "r"(b0), "r"(b1));
}

// ---------------- SMEM layout (dynamic) ----------------
// shared block-wide:
#define SM_WE1T 0          // 6*32 f32 = 768B
#define SM_WE2  768        // 32*6 f32 = 768B
#define SM_WN1T 1536       // 6*64 f32 = 1536B
#define SM_BE2  3072       // 8 f32 = 32B
#define SM_WARP 3104       // per-warp buffers start (16B aligned)
// per-warp buffer (17920B):
//   GA: 32 rows x 144B (gather A; later h2-hi mma plane)
//   GB: 32 rows x 144B (gather B; later h2-lo mma plane)
//   GC: 32 rows x 272B (gather C: 64 floats + pad; later nm staging rows x144)
#define W_GA 0
#define W_GB 4608
#define W_GC 9216
#define W_SIZE 17920
#define A_STRIDE 144
#define C_STRIDE 272
#define SM_TOTAL (SM_WARP + 4 * W_SIZE)    // 74784 bytes

// ================= precompute kernel: per-node projections =================
__global__ void __launch_bounds__(128) mpn_precompute_kernel(
    const float* __restrict__ x_node,
    const float* __restrict__ We1, const float* __restrict__ be1,
    const float* __restrict__ Wn1, const float* __restrict__ bn1)
{
    __shared__ __align__(16) float sW1[64 * 32];
    __shared__ __align__(16) float sWn[32 * 64];
    __shared__ __align__(16) float sbe1[32];
    __shared__ __align__(16) float sbn1[64];

    const int t = threadIdx.x;
    for (int i = t; i < 64 * 32; i += 128) sW1[i] = We1[i];
    for (int i = t; i < 32 * 64; i += 128) sWn[i] = Wn1[i];
    if (t < 32) sbe1[t] = be1[t];
    if (t < 64) sbn1[t] = bn1[t];
    __syncthreads();

    const int n = blockIdx.x * 128 + t;
    if (n >= N_NODES) return;

    float x[32];
    {
        const float4* px = reinterpret_cast<const float4*>(x_node + (size_t)n * 32);
#pragma unroll
        for (int i = 0; i < 8; i++) {
            float4 v = px[i];
            x[4*i] = v.x; x[4*i+1] = v.y; x[4*i+2] = v.z; x[4*i+3] = v.w;
        }
    }

    ull accA[16], accB[16], accC[32];
#pragma unroll
    for (int j = 0; j < 16; j++) {
        accA[j] = *reinterpret_cast<const ull*>(sbe1 + 2 * j);
        accB[j] = pack2(0.0f, 0.0f);
    }
#pragma unroll
    for (int j = 0; j < 32; j++)
        accC[j] = *reinterpret_cast<const ull*>(sbn1 + 2 * j);

#pragma unroll
    for (int i = 0; i < 32; i++) {
        ull ev = pack2(x[i], x[i]);
        const ulonglong2* wa = reinterpret_cast<const ulonglong2*>(sW1 + i * 32);
        const ulonglong2* wb = reinterpret_cast<const ulonglong2*>(sW1 + (32 + i) * 32);
        const ulonglong2* wc = reinterpret_cast<const ulonglong2*>(sWn + i * 64);
#pragma unroll
        for (int k = 0; k < 8; k++) {
            ulonglong2 w = wa[k];
            accA[2*k]   = fma2(ev, w.x, accA[2*k]);
            accA[2*k+1] = fma2(ev, w.y, accA[2*k+1]);
        }
#pragma unroll
        for (int k = 0; k < 8; k++) {
            ulonglong2 w = wb[k];
            accB[2*k]   = fma2(ev, w.x, accB[2*k]);
            accB[2*k+1] = fma2(ev, w.y, accB[2*k+1]);
        }
#pragma unroll
        for (int k = 0; k < 16; k++) {
            ulonglong2 w = wc[k];
            accC[2*k]   = fma2(ev, w.x, accC[2*k]);
            accC[2*k+1] = fma2(ev, w.y, accC[2*k+1]);
        }
    }

    ulonglong2* pA = reinterpret_cast<ulonglong2*>(g_A + (size_t)n * 32);
    ulonglong2* pB = reinterpret_cast<ulonglong2*>(g_B + (size_t)n * 32);
    ulonglong2* pC = reinterpret_cast<ulonglong2*>(g_C + (size_t)n * 64);
#pragma unroll
    for (int k = 0; k < 8; k++) pA[k] = make_ulonglong2(accA[2*k], accA[2*k+1]);
#pragma unroll
    for (int k = 0; k < 8; k++) pB[k] = make_ulonglong2(accB[2*k], accB[2*k+1]);
#pragma unroll
    for (int k = 0; k < 16; k++) pC[k] = make_ulonglong2(accC[2*k], accC[2*k+1]);
}

// ======= edge kernel: coalesced gathers/scatter, layer-4 warp mma.sync =====
__global__ void __launch_bounds__(128) mpn_edge_kernel(
    const float* __restrict__ x_edge,
    const int* __restrict__ src, const int* __restrict__ dst,
    const float* __restrict__ We1, const float* __restrict__ We2,
    const float* __restrict__ be2,
    const float* __restrict__ Wn1, const float* __restrict__ Wn2,
    const float* __restrict__ bn2,
    float* __restrict__ out_nm, float* __restrict__ out_em)
{
    extern __shared__ char smem[];
    const uint32_t smem_base = smem_u32(smem);
    const int t = threadIdx.x;
    const int wid = t >> 5;
    const int lane = t & 31;

    float* sWe1t = reinterpret_cast<float*>(smem + SM_WE1T);
    float* sWe2  = reinterpret_cast<float*>(smem + SM_WE2);
    float* sWn1t = reinterpret_cast<float*>(smem + SM_WN1T);
    float* sbe2  = reinterpret_cast<float*>(smem + SM_BE2);

    // ---- stage small weights ----
    for (int i = t; i < 6 * 32; i += 128)  sWe1t[i] = We1[64 * 32 + i];
    for (int i = t; i < 32 * 6; i += 128)  sWe2[i]  = We2[i];
    for (int i = t; i < 6 * 64; i += 128)  sWn1t[i] = Wn1[32 * 64 + i];
    if (t < 8)  sbe2[t] = (t < 6) ? be2[t] : 0.0f;
    __syncthreads();

    // ---- hoist Wn2 B-fragments (bf16 hi/lo) into registers, once ----
    const int col = lane >> 2;          // n within 8-col group
    const int krow = lane & 3;          // k-pair row within quad
    uint32_t Bh[4][4][2], Bl[4][4][2];
#pragma unroll
    for (int kt = 0; kt < 4; kt++) {
#pragma unroll
        for (int nt = 0; nt < 4; nt++) {
            int n = nt * 8 + col;
            int kp0 = kt * 8 + krow;
            int kp1 = kp0 + 4;
            float w00 = Wn2[(2 * kp0) * 32 + n];
            float w01 = Wn2[(2 * kp0 + 1) * 32 + n];
            float w10 = Wn2[(2 * kp1) * 32 + n];
            float w11 = Wn2[(2 * kp1 + 1) * 32 + n];
            uint32_t u00 = __float_as_uint(w00), u01 = __float_as_uint(w01);
            uint32_t u10 = __float_as_uint(w10), u11 = __float_as_uint(w11);
            Bh[kt][nt][0] = __byte_perm(u00, u01, 0x7632);
            Bh[kt][nt][1] = __byte_perm(u10, u11, 0x7632);
            float l00 = w00 - __uint_as_float(u00 & 0xFFFF0000u);
            float l01 = w01 - __uint_as_float(u01 & 0xFFFF0000u);
            float l10 = w10 - __uint_as_float(u10 & 0xFFFF0000u);
            float l11 = w11 - __uint_as_float(u11 & 0xFFFF0000u);
            uint32_t p0, p1;
            asm("cvt.rn.bf16x2.f32 %0, %1, %2;" : "=r"(p0) : "f"(l01), "f"(l00));
            asm("cvt.rn.bf16x2.f32 %0, %1, %2;" : "=r"(p1) : "f"(l11), "f"(l10));
            Bl[kt][nt][0] = p0;
            Bl[kt][nt][1] = p1;
        }
    }

    // epilogue bias pairs: cols nt*8 + (lane&3)*2, +1
    float2 bias[4];
    {
        const float2* b2 = reinterpret_cast<const float2*>(bn2);
#pragma unroll
        for (int nt = 0; nt < 4; nt++) bias[nt] = b2[nt * 4 + krow];
    }

    char* wbuf = smem + SM_WARP + wid * W_SIZE;
    const uint32_t wbuf_u = smem_base + SM_WARP + wid * W_SIZE;
    const uint32_t a_hi_base = wbuf_u + W_GA;
    const uint32_t a_lo_base = wbuf_u + W_GB;
    const uint32_t lds_lane_off = (uint32_t)(lane & 15) * A_STRIDE + (uint32_t)(lane >> 4) * 16;
    const int sub = lane >> 3;          // 0..3 : which edge within a gather instr
    const int qe  = lane & 7;           // 0..7 : 16B chunk within a 128B row

    for (int it = 0; it < NITER; it++) {
        const int e = (blockIdx.x * NITER + it) * 128 + wid * 32 + lane;
        const int s = src[e];
        const int d = dst[e];

        // ======== cooperative gathers into smem ========
#pragma unroll
        for (int j = 0; j < 8; j++) {               // A rows (dst-indexed)
            int eloc = 4 * j + sub;
            int dn = __shfl_sync(0xFFFFFFFFu, d, eloc);
            uint4 v = *reinterpret_cast<const uint4*>(g_A + (size_t)dn * 32 + qe * 4);
            *reinterpret_cast<uint4*>(wbuf + W_GA + eloc * A_STRIDE + qe * 16) = v;
        }
#pragma unroll
        for (int j = 0; j < 8; j++) {               // B rows (src-indexed)
            int eloc = 4 * j + sub;
            int sn = __shfl_sync(0xFFFFFFFFu, s, eloc);
            uint4 v = *reinterpret_cast<const uint4*>(g_B + (size_t)sn * 32 + qe * 4);
            *reinterpret_cast<uint4*>(wbuf + W_GB + eloc * A_STRIDE + qe * 16) = v;
        }
#pragma unroll
        for (int j = 0; j < 16; j++) {              // C rows (dst-indexed, 256B each)
            int c = 4 * j + sub;
            int eloc = c >> 1, half = c & 1;
            int dn = __shfl_sync(0xFFFFFFFFu, d, eloc);
            uint4 v = *reinterpret_cast<const uint4*>(g_C + (size_t)dn * 64 + half * 32 + qe * 4);
            *reinterpret_cast<uint4*>(wbuf + W_GC + eloc * C_STRIDE + half * 128 + qe * 16) = v;
        }
        __syncwarp();

        // ======== layer 1: acc1 = A[d] + B[s] + xe @ We1[64:70] ========
        ull acc1[16];
        {
            const longlong2* ra = reinterpret_cast<const longlong2*>(wbuf + W_GA + lane * A_STRIDE);
            const longlong2* rb = reinterpret_cast<const longlong2*>(wbuf + W_GB + lane * A_STRIDE);
#pragma unroll
            for (int k = 0; k < 8; k++) {
                longlong2 a = ra[k], b = rb[k];
                acc1[2*k]   = add2((ull)a.x, (ull)b.x);
                acc1[2*k+1] = add2((ull)a.y, (ull)b.y);
            }
        }
        float xe[6];
        {
            const float2* pe = reinterpret_cast<const float2*>(x_edge + (size_t)e * 6);
            float2 a = pe[0], b = pe[1], c = pe[2];
            xe[0]=a.x; xe[1]=a.y; xe[2]=b.x; xe[3]=b.y; xe[4]=c.x; xe[5]=c.y;
        }
#pragma unroll
        for (int i = 0; i < 6; i++) {
            ull ev = pack2(xe[i], xe[i]);
            const ulonglong2* w = reinterpret_cast<const ulonglong2*>(sWe1t + i * 32);
#pragma unroll
            for (int k = 0; k < 8; k++) {
                ulonglong2 wp = w[k];
                acc1[2*k]   = fma2(ev, wp.x, acc1[2*k]);
                acc1[2*k+1] = fma2(ev, wp.y, acc1[2*k+1]);
            }
        }
        float h1[32];
#pragma unroll
        for (int j = 0; j < 16; j++) relu2(acc1[j], h1[2*j], h1[2*j+1]);

        // ======== layer 2: em = relu(h1 @ We2 + be2) ========
        ull acc2[3];
#pragma unroll
        for (int j = 0; j < 3; j++) acc2[j] = *reinterpret_cast<const ull*>(sbe2 + 2 * j);
#pragma unroll
        for (int i = 0; i < 32; i++) {
            const ull* w = reinterpret_cast<const ull*>(sWe2 + i * 6);
            ull ev = pack2(h1[i], h1[i]);
            acc2[0] = fma2(ev, w[0], acc2[0]);
            acc2[1] = fma2(ev, w[1], acc2[1]);
            acc2[2] = fma2(ev, w[2], acc2[2]);
        }
        float em[6];
#pragma unroll
        for (int j = 0; j < 3; j++) relu2(acc2[j], em[2*j], em[2*j+1]);
        {
            float2* po = reinterpret_cast<float2*>(out_em + (size_t)e * 6);
            po[0] = make_float2(em[0], em[1]);
            po[1] = make_float2(em[2], em[3]);
            po[2] = make_float2(em[4], em[5]);
        }

        // ======== layer 3: h2 = relu(C[d] + em @ Wn1[32:38]); bf16 hi/lo ====
        uint32_t ahi[32], alo[32];
        ull emv[6];
#pragma unroll
        for (int i = 0; i < 6; i++) emv[i] = pack2(em[i], em[i]);

        const char* rowC = wbuf + W_GC + lane * C_STRIDE;
#pragma unroll
        for (int c = 0; c < 4; c++) {
            ull acc3[8];
            const longlong2* pc = reinterpret_cast<const longlong2*>(rowC + c * 64);
#pragma unroll
            for (int k = 0; k < 4; k++) {
                longlong2 v = pc[k];
                acc3[2*k] = (ull)v.x; acc3[2*k+1] = (ull)v.y;
            }
#pragma unroll
            for (int i = 0; i < 6; i++) {
                const ulonglong2* w = reinterpret_cast<const ulonglong2*>(sWn1t + i * 64 + c * 16);
#pragma unroll
                for (int k = 0; k < 4; k++) {
                    ulonglong2 wp = w[k];
                    acc3[2*k]   = fma2(emv[i], wp.x, acc3[2*k]);
                    acc3[2*k+1] = fma2(emv[i], wp.y, acc3[2*k+1]);
                }
            }
#pragma unroll
            for (int j = 0; j < 8; j++) {
                float a, b;
                relu2(acc3[j], a, b);
                uint32_t ua = __float_as_uint(a);
                uint32_t ub = __float_as_uint(b);
                float la = a - __uint_as_float(ua & 0xFFFF0000u);
                float lb = b - __uint_as_float(ub & 0xFFFF0000u);
                ahi[c * 8 + j] = __byte_perm(ua, ub, 0x7632);
                uint32_t lp;
                asm("cvt.rn.bf16x2.f32 %0, %1, %2;" : "=r"(lp) : "f"(lb), "f"(la));
                alo[c * 8 + j] = lp;
            }
        }
        __syncwarp();   // everyone done reading gA/gB before overwrite with h2 planes

        // ---- stage h2 hi/lo rows (row = this lane's edge), overlaying GA/GB ----
        {
            uint4* rh = reinterpret_cast<uint4*>(wbuf + W_GA + lane * A_STRIDE);
            uint4* rl = reinterpret_cast<uint4*>(wbuf + W_GB + lane * A_STRIDE);
#pragma unroll
            for (int i = 0; i < 8; i++) {
                rh[i] = make_uint4(ahi[4*i], ahi[4*i+1], ahi[4*i+2], ahi[4*i+3]);
                rl[i] = make_uint4(alo[4*i], alo[4*i+1], alo[4*i+2], alo[4*i+3]);
            }
        }
        __syncwarp();

        // ======== layer 4: C[32x32] = Ahi@(Bhi+Blo) + Alo@Bhi via mma.sync ===
        float acc[8][4];
#pragma unroll
        for (int f = 0; f < 8; f++) {
            acc[f][0] = 0.0f; acc[f][1] = 0.0f; acc[f][2] = 0.0f; acc[f][3] = 0.0f;
        }
#pragma unroll
        for (int kt = 0; kt < 4; kt++) {
            uint32_t a0[4], a1[4];
            ldsm_x4(a0, a_hi_base + lds_lane_off + kt * 32);
            ldsm_x4(a1, a_hi_base + lds_lane_off + 16 * A_STRIDE + kt * 32);
#pragma unroll
            for (int nt = 0; nt < 4; nt++) {
                mma_bf16(acc[nt],     a0, Bh[kt][nt][0], Bh[kt][nt][1]);
                mma_bf16(acc[nt],     a0, Bl[kt][nt][0], Bl[kt][nt][1]);
                mma_bf16(acc[4 + nt], a1, Bh[kt][nt][0], Bh[kt][nt][1]);
                mma_bf16(acc[4 + nt], a1, Bl[kt][nt][0], Bl[kt][nt][1]);
            }
        }
#pragma unroll
        for (int kt = 0; kt < 4; kt++) {
            uint32_t a0[4], a1[4];
            ldsm_x4(a0, a_lo_base + lds_lane_off + kt * 32);
            ldsm_x4(a1, a_lo_base + lds_lane_off + 16 * A_STRIDE + kt * 32);
#pragma unroll
            for (int nt = 0; nt < 4; nt++) {
                mma_bf16(acc[nt],     a0, Bh[kt][nt][0], Bh[kt][nt][1]);
                mma_bf16(acc[4 + nt], a1, Bh[kt][nt][0], Bh[kt][nt][1]);
            }
        }

        // ======== epilogue: bias+relu -> smem rows (overlay GC), coop scatter =
        const int r = lane >> 2;
        const int cb = krow * 2;
        char* nmbase = wbuf + W_GC;
#pragma unroll
        for (int mt = 0; mt < 2; mt++) {
#pragma unroll
            for (int nt = 0; nt < 4; nt++) {
                const float* a = acc[mt * 4 + nt];
                float v0 = fmaxf(a[0] + bias[nt].x, 0.0f);
                float v1 = fmaxf(a[1] + bias[nt].y, 0.0f);
                float v2 = fmaxf(a[2] + bias[nt].x, 0.0f);
                float v3 = fmaxf(a[3] + bias[nt].y, 0.0f);
                *reinterpret_cast<float2*>(nmbase + (mt * 16 + r) * A_STRIDE + (nt * 8 + cb) * 4)
                    = make_float2(v0, v1);
                *reinterpret_cast<float2*>(nmbase + (mt * 16 + r + 8) * A_STRIDE + (nt * 8 + cb) * 4)
                    = make_float2(v2, v3);
            }
        }
        __syncwarp();

#pragma unroll
        for (int j = 0; j < 8; j++) {
            int eloc = 4 * j + sub;
            int dn = __shfl_sync(0xFFFFFFFFu, d, eloc);
            float4 v = *reinterpret_cast<const float4*>(nmbase + eloc * A_STRIDE + qe * 16);
            asm volatile("red.global.add.v4.f32 [%0], {%1, %2, %3, %4};"
                         :: "l"(out_nm + (size_t)dn * 32 + qe * 4),
                            "f"(v.x), "f"(v.y), "f"(v.z), "f"(v.w) : "memory");
        }
        __syncwarp();   // nm smem reads done before next iter's C gather overwrites
    }
}

extern "C" void kernel_launch(void* const* d_in, const int* in_sizes, int n_in,
                              void* d_out, int out_size) {
    const float* x_node = (const float*)d_in[0];
    const float* x_edge = (const float*)d_in[1];
    const int*   src    = (const int*)d_in[2];
    const int*   dst    = (const int*)d_in[3];
    const float* We1    = (const float*)d_in[4];
    const float* be1    = (const float*)d_in[5];
    const float* We2    = (const float*)d_in[6];
    const float* be2    = (const float*)d_in[7];
    const float* Wn1    = (const float*)d_in[8];
    const float* bn1    = (const float*)d_in[9];
    const float* Wn2    = (const float*)d_in[10];
    const float* bn2    = (const float*)d_in[11];

    float* out    = (float*)d_out;
    float* out_nm = out;                        // [N_NODES, 32]
    float* out_em = out + (size_t)N_NODES * 32; // [N_EDGES, 6]

    cudaFuncSetAttribute(mpn_edge_kernel,
                         cudaFuncAttributeMaxDynamicSharedMemorySize, SM_TOTAL);

    cudaMemsetAsync(out_nm, 0, (size_t)N_NODES * 32 * sizeof(float));

    mpn_precompute_kernel<<<(N_NODES + 127) / 128, 128>>>(x_node, We1, be1, Wn1, bn1);

    mpn_edge_kernel<<<GRID_EDGE, 128, SM_TOTAL>>>(x_edge, src, dst,
                                                  We1, We2, be2, Wn1, Wn2, bn2,
                                                  out_nm, out_em);
}

// round 10
// speedup vs baseline: 3.8288x; 1.3078x over previous
#include <cuda_runtime.h>
#include <cuda_bf16.h>
#include <cstddef>
#include <cstdint>

#define N_NODES 100000
#define N_EDGES 3200000
#define NITER 8                 // 128-edge tiles per block
#define GRID_EDGE 3125          // 3125 * 8 * 128 = 3,200,000

typedef unsigned long long ull;

// Per-node precomputed projections (static device scratch — allowed).
__device__ float g_A[(size_t)N_NODES * 32];  // be1 + x@We1[0:32,:]
__device__ float g_B[(size_t)N_NODES * 32];  // x@We1[32:64,:]
__device__ float g_C[(size_t)N_NODES * 64];  // bn1 + x@Wn1[0:32,:]

// Small weights in constant memory -> warp-uniform LDCU, zero L1 wavefronts.
__constant__ float c_We1t[6 * 32];   // We1 rows 64..69
__constant__ float c_We2[32 * 6];
__constant__ float c_Wn1t[6 * 64];   // Wn1 rows 32..37
__constant__ float c_be2[6];
__constant__ float c_bn2[32];

// ---------------- packed f32x2 helpers ----------------
__device__ __forceinline__ ull pack2(float a, float b) {
    ull r; asm("mov.b64 %0, {%1, %2};" : "=l"(r) : "f"(a), "f"(b)); return r;
}
__device__ __forceinline__ void unpack2(ull v, float& a, float& b) {
    asm("mov.b64 {%0, %1}, %2;" : "=f"(a), "=f"(b) : "l"(v));
}
__device__ __forceinline__ ull fma2(ull a, ull b, ull c) {
    ull d; asm("fma.rn.f32x2 %0, %1, %2, %3;" : "=l"(d) : "l"(a), "l"(b), "l"(c)); return d;
}
__device__ __forceinline__ ull add2(ull a, ull b) {
    ull d; asm("add.rn.f32x2 %0, %1, %2;" : "=l"(d) : "l"(a), "l"(b)); return d;
}
__device__ __forceinline__ void relu2(ull v, float& a, float& b) {
    unpack2(v, a, b);
    a = fmaxf(a, 0.0f);
    b = fmaxf(b, 0.0f);
}

__device__ __forceinline__ uint32_t smem_u32(const void* p) {
    uint32_t a;
    asm("{ .reg .u64 tmp; cvta.to.shared.u64 tmp, %1; cvt.u32.u64 %0, tmp; }"
        : "=r"(a) : "l"(p));
    return a;
}

// ---------------- warp MMA helpers (sm_80-era PTX, safe at compute_103) ----
__device__ __forceinline__ void ldsm_x4(uint32_t* r, uint32_t addr) {
    asm volatile("ldmatrix.sync.aligned.m8n8.x4.shared.b16 {%0,%1,%2,%3}, [%4];"
                 : "=r"(r[0]), "=r"(r[1]), "=r"(r[2]), "=r"(r[3]) : "r"(addr));
}
__device__ __forceinline__ void mma_bf16(float* c, const uint32_t* a,
                                         uint32_t b0, uint32_t b1) {
    asm volatile(
        "mma.sync.aligned.m16n8k16.row.col.f32.bf16.bf16.f32 "
        "{%0,%1,%2,%3}, {%4,%5,%6,%7}, {%8,%9}, {%0,%1,%2,%3};"
        : "+f"(c[0]), "+f"(c[1]), "+f"(c[2]), "+f"(c[3])
        : "r"(a[0]), "r"(a[1]), "r"(a[2]), "r"(a[3]), "r"(b0), "r"(b1));
}

// ---------------- SMEM layout (dynamic): per-warp buffers only ------------
// per-warp buffer (17920B):
//   GA: 32 rows x 144B (gather A; later h2-hi mma plane)
//   GB: 32 rows x 144B (gather B; later h2-lo mma plane)
//   GC: 32 rows x 272B (gather C; later nm staging rows x144)
#define W_GA 0
#define W_GB 4608
#define W_GC 9216
#define W_SIZE 17920
#define A_STRIDE 144
#define C_STRIDE 272
#define SM_TOTAL (4 * W_SIZE)    // 71680 bytes -> 3 CTAs/SM

// ================= precompute kernel: per-node projections =================
__global__ void __launch_bounds__(128) mpn_precompute_kernel(
    const float* __restrict__ x_node,
    const float* __restrict__ We1, const float* __restrict__ be1,
    const float* __restrict__ Wn1, const float* __restrict__ bn1)
{
    __shared__ __align__(16) float sW1[64 * 32];
    __shared__ __align__(16) float sWn[32 * 64];
    __shared__ __align__(16) float sbe1[32];
    __shared__ __align__(16) float sbn1[64];

    const int t = threadIdx.x;
    for (int i = t; i < 64 * 32; i += 128) sW1[i] = We1[i];
    for (int i = t; i < 32 * 64; i += 128) sWn[i] = Wn1[i];
    if (t < 32) sbe1[t] = be1[t];
    if (t < 64) sbn1[t] = bn1[t];
    __syncthreads();

    const int n = blockIdx.x * 128 + t;
    if (n >= N_NODES) return;

    float x[32];
    {
        const float4* px = reinterpret_cast<const float4*>(x_node + (size_t)n * 32);
#pragma unroll
        for (int i = 0; i < 8; i++) {
            float4 v = px[i];
            x[4*i] = v.x; x[4*i+1] = v.y; x[4*i+2] = v.z; x[4*i+3] = v.w;
        }
    }

    ull accA[16], accB[16], accC[32];
#pragma unroll
    for (int j = 0; j < 16; j++) {
        accA[j] = *reinterpret_cast<const ull*>(sbe1 + 2 * j);
        accB[j] = pack2(0.0f, 0.0f);
    }
#pragma unroll
    for (int j = 0; j < 32; j++)
        accC[j] = *reinterpret_cast<const ull*>(sbn1 + 2 * j);

#pragma unroll
    for (int i = 0; i < 32; i++) {
        ull ev = pack2(x[i], x[i]);
        const ulonglong2* wa = reinterpret_cast<const ulonglong2*>(sW1 + i * 32);
        const ulonglong2* wb = reinterpret_cast<const ulonglong2*>(sW1 + (32 + i) * 32);
        const ulonglong2* wc = reinterpret_cast<const ulonglong2*>(sWn + i * 64);
#pragma unroll
        for (int k = 0; k < 8; k++) {
            ulonglong2 w = wa[k];
            accA[2*k]   = fma2(ev, w.x, accA[2*k]);
            accA[2*k+1] = fma2(ev, w.y, accA[2*k+1]);
        }
#pragma unroll
        for (int k = 0; k < 8; k++) {
            ulonglong2 w = wb[k];
            accB[2*k]   = fma2(ev, w.x, accB[2*k]);
            accB[2*k+1] = fma2(ev, w.y, accB[2*k+1]);
        }
#pragma unroll
        for (int k = 0; k < 16; k++) {
            ulonglong2 w = wc[k];
            accC[2*k]   = fma2(ev, w.x, accC[2*k]);
            accC[2*k+1] = fma2(ev, w.y, accC[2*k+1]);
        }
    }

    ulonglong2* pA = reinterpret_cast<ulonglong2*>(g_A + (size_t)n * 32);
    ulonglong2* pB = reinterpret_cast<ulonglong2*>(g_B + (size_t)n * 32);
    ulonglong2* pC = reinterpret_cast<ulonglong2*>(g_C + (size_t)n * 64);
#pragma unroll
    for (int k = 0; k < 8; k++) pA[k] = make_ulonglong2(accA[2*k], accA[2*k+1]);
#pragma unroll
    for (int k = 0; k < 8; k++) pB[k] = make_ulonglong2(accB[2*k], accB[2*k+1]);
#pragma unroll
    for (int k = 0; k < 16; k++) pC[k] = make_ulonglong2(accC[2*k], accC[2*k+1]);
}

// ======= edge kernel: coalesced gathers/scatter, layer-4 warp mma.sync =====
__global__ void __launch_bounds__(128, 3) mpn_edge_kernel(
    const float* __restrict__ x_edge,
    const int* __restrict__ src, const int* __restrict__ dst,
    const float* __restrict__ Wn2,
    float* __restrict__ out_nm, float* __restrict__ out_em)
{
    extern __shared__ char smem[];
    const uint32_t smem_base = smem_u32(smem);
    const int t = threadIdx.x;
    const int wid = t >> 5;
    const int lane = t & 31;

    // ---- hoist Wn2 B-fragments (bf16 hi/lo) into registers, once ----
    const int col = lane >> 2;          // n within 8-col group
    const int krow = lane & 3;          // k-pair row within quad
    uint32_t Bh[4][4][2], Bl[4][4][2];
#pragma unroll
    for (int kt = 0; kt < 4; kt++) {
#pragma unroll
        for (int nt = 0; nt < 4; nt++) {
            int n = nt * 8 + col;
            int kp0 = kt * 8 + krow;
            int kp1 = kp0 + 4;
            float w00 = Wn2[(2 * kp0) * 32 + n];
            float w01 = Wn2[(2 * kp0 + 1) * 32 + n];
            float w10 = Wn2[(2 * kp1) * 32 + n];
            float w11 = Wn2[(2 * kp1 + 1) * 32 + n];
            uint32_t u00 = __float_as_uint(w00), u01 = __float_as_uint(w01);
            uint32_t u10 = __float_as_uint(w10), u11 = __float_as_uint(w11);
            Bh[kt][nt][0] = __byte_perm(u00, u01, 0x7632);
            Bh[kt][nt][1] = __byte_perm(u10, u11, 0x7632);
            float l00 = w00 - __uint_as_float(u00 & 0xFFFF0000u);
            float l01 = w01 - __uint_as_float(u01 & 0xFFFF0000u);
            float l10 = w10 - __uint_as_float(u10 & 0xFFFF0000u);
            float l11 = w11 - __uint_as_float(u11 & 0xFFFF0000u);
            uint32_t p0, p1;
            asm("cvt.rn.bf16x2.f32 %0, %1, %2;" : "=r"(p0) : "f"(l01), "f"(l00));
            asm("cvt.rn.bf16x2.f32 %0, %1, %2;" : "=r"(p1) : "f"(l11), "f"(l10));
            Bl[kt][nt][0] = p0;
            Bl[kt][nt][1] = p1;
        }
    }

    // epilogue bias pairs: cols nt*8 + krow*2, +1
    float2 bias[4];
#pragma unroll
    for (int nt = 0; nt < 4; nt++)
        bias[nt] = make_float2(c_bn2[nt * 8 + krow * 2], c_bn2[nt * 8 + krow * 2 + 1]);

    char* wbuf = smem + wid * W_SIZE;
    const uint32_t wbuf_u = smem_base + wid * W_SIZE;
    const uint32_t a_hi_base = wbuf_u + W_GA;
    const uint32_t a_lo_base = wbuf_u + W_GB;
    const uint32_t lds_lane_off = (uint32_t)(lane & 15) * A_STRIDE + (uint32_t)(lane >> 4) * 16;
    const int sub = lane >> 3;          // 0..3 : which edge within a gather instr
    const int qe  = lane & 7;           // 0..7 : 16B chunk within a 128B row

    for (int it = 0; it < NITER; it++) {
        const int e = (blockIdx.x * NITER + it) * 128 + wid * 32 + lane;
        const int s = src[e];
        const int d = dst[e];

        // ======== cooperative gathers into smem ========
#pragma unroll
        for (int j = 0; j < 8; j++) {               // A rows (dst-indexed)
            int eloc = 4 * j + sub;
            int dn = __shfl_sync(0xFFFFFFFFu, d, eloc);
            uint4 v = *reinterpret_cast<const uint4*>(g_A + (size_t)dn * 32 + qe * 4);
            *reinterpret_cast<uint4*>(wbuf + W_GA + eloc * A_STRIDE + qe * 16) = v;
        }
#pragma unroll
        for (int j = 0; j < 8; j++) {               // B rows (src-indexed)
            int eloc = 4 * j + sub;
            int sn = __shfl_sync(0xFFFFFFFFu, s, eloc);
            uint4 v = *reinterpret_cast<const uint4*>(g_B + (size_t)sn * 32 + qe * 4);
            *reinterpret_cast<uint4*>(wbuf + W_GB + eloc * A_STRIDE + qe * 16) = v;
        }
#pragma unroll
        for (int j = 0; j < 16; j++) {              // C rows (dst-indexed, 256B each)
            int c = 4 * j + sub;
            int eloc = c >> 1, half = c & 1;
            int dn = __shfl_sync(0xFFFFFFFFu, d, eloc);
            uint4 v = *reinterpret_cast<const uint4*>(g_C + (size_t)dn * 64 + half * 32 + qe * 4);
            *reinterpret_cast<uint4*>(wbuf + W_GC + eloc * C_STRIDE + half * 128 + qe * 16) = v;
        }
        __syncwarp();

        // ======== layer 1: acc1 = A[d] + B[s] + xe @ We1[64:70] ========
        ull acc1[16];
        {
            const longlong2* ra = reinterpret_cast<const longlong2*>(wbuf + W_GA + lane * A_STRIDE);
            const longlong2* rb = reinterpret_cast<const longlong2*>(wbuf + W_GB + lane * A_STRIDE);
#pragma unroll
            for (int k = 0; k < 8; k++) {
                longlong2 a = ra[k], b = rb[k];
                acc1[2*k]   = add2((ull)a.x, (ull)b.x);
                acc1[2*k+1] = add2((ull)a.y, (ull)b.y);
            }
        }
        float xe[6];
        {
            const float2* pe = reinterpret_cast<const float2*>(x_edge + (size_t)e * 6);
            float2 a = pe[0], b = pe[1], c = pe[2];
            xe[0]=a.x; xe[1]=a.y; xe[2]=b.x; xe[3]=b.y; xe[4]=c.x; xe[5]=c.y;
        }
#pragma unroll
        for (int i = 0; i < 6; i++) {
            ull ev = pack2(xe[i], xe[i]);
            const ulonglong2* w = reinterpret_cast<const ulonglong2*>(c_We1t + i * 32);
#pragma unroll
            for (int k = 0; k < 8; k++) {
                ulonglong2 wp = w[k];
                acc1[2*k]   = fma2(ev, wp.x, acc1[2*k]);
                acc1[2*k+1] = fma2(ev, wp.y, acc1[2*k+1]);
            }
        }
        float h1[32];
#pragma unroll
        for (int j = 0; j < 16; j++) relu2(acc1[j], h1[2*j], h1[2*j+1]);

        // ======== layer 2: em = relu(h1 @ We2 + be2) ========
        ull acc2[3];
#pragma unroll
        for (int j = 0; j < 3; j++) acc2[j] = *reinterpret_cast<const ull*>(c_be2 + 2 * j);
#pragma unroll
        for (int i = 0; i < 32; i++) {
            const ull* w = reinterpret_cast<const ull*>(c_We2 + i * 6);
            ull ev = pack2(h1[i], h1[i]);
            acc2[0] = fma2(ev, w[0], acc2[0]);
            acc2[1] = fma2(ev, w[1], acc2[1]);
            acc2[2] = fma2(ev, w[2], acc2[2]);
        }
        float em[6];
#pragma unroll
        for (int j = 0; j < 3; j++) relu2(acc2[j], em[2*j], em[2*j+1]);
        {
            float2* po = reinterpret_cast<float2*>(out_em + (size_t)e * 6);
            po[0] = make_float2(em[0], em[1]);
            po[1] = make_float2(em[2], em[3]);
            po[2] = make_float2(em[4], em[5]);
        }

        // ======== layer 3: h2 = relu(C[d] + em @ Wn1[32:38]) ========
        // stream bf16 hi/lo planes straight to smem (own row only -> no sync
        // needed vs layer-1 own-row reads)
        ull emv[6];
#pragma unroll
        for (int i = 0; i < 6; i++) emv[i] = pack2(em[i], em[i]);

        const char* rowC = wbuf + W_GC + lane * C_STRIDE;
        char* rowH = wbuf + W_GA + lane * A_STRIDE;
        char* rowL = wbuf + W_GB + lane * A_STRIDE;
#pragma unroll
        for (int c = 0; c < 4; c++) {
            ull acc3[8];
            const longlong2* pc = reinterpret_cast<const longlong2*>(rowC + c * 64);
#pragma unroll
            for (int k = 0; k < 4; k++) {
                longlong2 v = pc[k];
                acc3[2*k] = (ull)v.x; acc3[2*k+1] = (ull)v.y;
            }
#pragma unroll
            for (int i = 0; i < 6; i++) {
                const ulonglong2* w = reinterpret_cast<const ulonglong2*>(c_Wn1t + i * 64 + c * 16);
#pragma unroll
                for (int k = 0; k < 4; k++) {
                    ulonglong2 wp = w[k];
                    acc3[2*k]   = fma2(emv[i], wp.x, acc3[2*k]);
                    acc3[2*k+1] = fma2(emv[i], wp.y, acc3[2*k+1]);
                }
            }
            uint32_t hi[8], lo[8];
#pragma unroll
            for (int j = 0; j < 8; j++) {
                float a, b;
                relu2(acc3[j], a, b);
                uint32_t ua = __float_as_uint(a);
                uint32_t ub = __float_as_uint(b);
                float la = a - __uint_as_float(ua & 0xFFFF0000u);
                float lb = b - __uint_as_float(ub & 0xFFFF0000u);
                hi[j] = __byte_perm(ua, ub, 0x7632);
                asm("cvt.rn.bf16x2.f32 %0, %1, %2;" : "=r"(lo[j]) : "f"(lb), "f"(la));
            }
            reinterpret_cast<uint4*>(rowH)[2*c]     = make_uint4(hi[0], hi[1], hi[2], hi[3]);
            reinterpret_cast<uint4*>(rowH)[2*c + 1] = make_uint4(hi[4], hi[5], hi[6], hi[7]);
            reinterpret_cast<uint4*>(rowL)[2*c]     = make_uint4(lo[0], lo[1], lo[2], lo[3]);
            reinterpret_cast<uint4*>(rowL)[2*c + 1] = make_uint4(lo[4], lo[5], lo[6], lo[7]);
        }
        __syncwarp();

        // ======== layer 4: C[32x32] = Ahi@(Bhi+Blo) + Alo@Bhi via mma.sync ===
        float acc[8][4];
#pragma unroll
        for (int f = 0; f < 8; f++) {
            acc[f][0] = 0.0f; acc[f][1] = 0.0f; acc[f][2] = 0.0f; acc[f][3] = 0.0f;
        }
#pragma unroll
        for (int kt = 0; kt < 4; kt++) {
            uint32_t a0[4], a1[4];
            ldsm_x4(a0, a_hi_base + lds_lane_off + kt * 32);
            ldsm_x4(a1, a_hi_base + lds_lane_off + 16 * A_STRIDE + kt * 32);
#pragma unroll
            for (int nt = 0; nt < 4; nt++) {
                mma_bf16(acc[nt],     a0, Bh[kt][nt][0], Bh[kt][nt][1]);
                mma_bf16(acc[nt],     a0, Bl[kt][nt][0], Bl[kt][nt][1]);
                mma_bf16(acc[4 + nt], a1, Bh[kt][nt][0], Bh[kt][nt][1]);
                mma_bf16(acc[4 + nt], a1, Bl[kt][nt][0], Bl[kt][nt][1]);
            }
        }
#pragma unroll
        for (int kt = 0; kt < 4; kt++) {
            uint32_t a0[4], a1[4];
            ldsm_x4(a0, a_lo_base + lds_lane_off + kt * 32);
            ldsm_x4(a1, a_lo_base + lds_lane_off + 16 * A_STRIDE + kt * 32);
#pragma unroll
            for (int nt = 0; nt < 4; nt++) {
                mma_bf16(acc[nt],     a0, Bh[kt][nt][0], Bh[kt][nt][1]);
                mma_bf16(acc[4 + nt], a1, Bh[kt][nt][0], Bh[kt][nt][1]);
            }
        }

        // ======== epilogue: bias+relu -> smem rows (overlay GC), coop scatter =
        const int r = lane >> 2;
        const int cb = krow * 2;
        char* nmbase = wbuf + W_GC;
#pragma unroll
        for (int mt = 0; mt < 2; mt++) {
#pragma unroll
            for (int nt = 0; nt < 4; nt++) {
                const float* a = acc[mt * 4 + nt];
                float v0 = fmaxf(a[0] + bias[nt].x, 0.0f);
                float v1 = fmaxf(a[1] + bias[nt].y, 0.0f);
                float v2 = fmaxf(a[2] + bias[nt].x, 0.0f);
                float v3 = fmaxf(a[3] + bias[nt].y, 0.0f);
                *reinterpret_cast<float2*>(nmbase + (mt * 16 + r) * A_STRIDE + (nt * 8 + cb) * 4)
                    = make_float2(v0, v1);
                *reinterpret_cast<float2*>(nmbase + (mt * 16 + r + 8) * A_STRIDE + (nt * 8 + cb) * 4)
                    = make_float2(v2, v3);
            }
        }
        __syncwarp();

#pragma unroll
        for (int j = 0; j < 8; j++) {
            int eloc = 4 * j + sub;
            int dn = __shfl_sync(0xFFFFFFFFu, d, eloc);
            float4 v = *reinterpret_cast<const float4*>(nmbase + eloc * A_STRIDE + qe * 16);
            asm volatile("red.global.add.v4.f32 [%0], {%1, %2, %3, %4};"
                         :: "l"(out_nm + (size_t)dn * 32 + qe * 4),
                            "f"(v.x), "f"(v.y), "f"(v.z), "f"(v.w) : "memory");
        }
        __syncwarp();   // nm smem reads done before next iter's C gather overwrites
    }
}

extern "C" void kernel_launch(void* const* d_in, const int* in_sizes, int n_in,
                              void* d_out, int out_size) {
    const float* x_node = (const float*)d_in[0];
    const float* x_edge = (const float*)d_in[1];
    const int*   src    = (const int*)d_in[2];
    const int*   dst    = (const int*)d_in[3];
    const float* We1    = (const float*)d_in[4];
    const float* be1    = (const float*)d_in[5];
    const float* We2    = (const float*)d_in[6];
    const float* be2    = (const float*)d_in[7];
    const float* Wn1    = (const float*)d_in[8];
    const float* bn1    = (const float*)d_in[9];
    const float* Wn2    = (const float*)d_in[10];
    const float* bn2    = (const float*)d_in[11];

    float* out    = (float*)d_out;
    float* out_nm = out;                        // [N_NODES, 32]
    float* out_em = out + (size_t)N_NODES * 32; // [N_EDGES, 6]

    cudaFuncSetAttribute(mpn_edge_kernel,
                         cudaFuncAttributeMaxDynamicSharedMemorySize, SM_TOTAL);

    // Stage small weights into constant memory (async D2D, graph-capturable).
    cudaMemcpyToSymbolAsync(c_We1t, We1 + 64 * 32, 6 * 32 * sizeof(float), 0,
                            cudaMemcpyDeviceToDevice);
    cudaMemcpyToSymbolAsync(c_We2, We2, 32 * 6 * sizeof(float), 0,
                            cudaMemcpyDeviceToDevice);
    cudaMemcpyToSymbolAsync(c_Wn1t, Wn1 + 32 * 64, 6 * 64 * sizeof(float), 0,
                            cudaMemcpyDeviceToDevice);
    cudaMemcpyToSymbolAsync(c_be2, be2, 6 * sizeof(float), 0,
                            cudaMemcpyDeviceToDevice);
    cudaMemcpyToSymbolAsync(c_bn2, bn2, 32 * sizeof(float), 0,
                            cudaMemcpyDeviceToDevice);

    cudaMemsetAsync(out_nm, 0, (size_t)N_NODES * 32 * sizeof(float));

    mpn_precompute_kernel<<<(N_NODES + 127) / 128, 128>>>(x_node, We1, be1, Wn1, bn1);

    mpn_edge_kernel<<<GRID_EDGE, 128, SM_TOTAL>>>(x_edge, src, dst, Wn2,
                                                  out_nm, out_em);
}

// round 11
// speedup vs baseline: 3.9374x; 1.0284x over previous
#include <cuda_runtime.h>
#include <cuda_bf16.h>
#include <cstddef>
#include <cstdint>

#define N_NODES 100000
#define N_EDGES 3200000
#define NITER 8                 // 128-edge tiles per block
#define GRID_EDGE 3125          // 3125 * 8 * 128 = 3,200,000

typedef unsigned long long ull;

// Per-node precomputed projections (static device scratch — allowed).
__device__ float g_A[(size_t)N_NODES * 32];  // be1 + x@We1[0:32,:]
__device__ float g_B[(size_t)N_NODES * 32];  // x@We1[32:64,:]
__device__ float g_C[(size_t)N_NODES * 64];  // bn1 + x@Wn1[0:32,:]

// Small weights in constant memory -> warp-uniform LDCU, zero L1 wavefronts.
__constant__ float c_We1t[6 * 32];   // We1 rows 64..69
__constant__ float c_We2[32 * 6];
__constant__ float c_Wn1t[6 * 64];   // Wn1 rows 32..37
__constant__ float c_be2[6];
__constant__ float c_bn2[32];

// ---------------- packed f32x2 helpers ----------------
__device__ __forceinline__ ull pack2(float a, float b) {
    ull r; asm("mov.b64 %0, {%1, %2};" : "=l"(r) : "f"(a), "f"(b)); return r;
}
__device__ __forceinline__ void unpack2(ull v, float& a, float& b) {
    asm("mov.b64 {%0, %1}, %2;" : "=f"(a), "=f"(b) : "l"(v));
}
__device__ __forceinline__ ull fma2(ull a, ull b, ull c) {
    ull d; asm("fma.rn.f32x2 %0, %1, %2, %3;" : "=l"(d) : "l"(a), "l"(b), "l"(c)); return d;
}
__device__ __forceinline__ ull add2(ull a, ull b) {
    ull d; asm("add.rn.f32x2 %0, %1, %2;" : "=l"(d) : "l"(a), "l"(b)); return d;
}
__device__ __forceinline__ void relu2(ull v, float& a, float& b) {
    unpack2(v, a, b);
    a = fmaxf(a, 0.0f);
    b = fmaxf(b, 0.0f);
}

__device__ __forceinline__ uint32_t smem_u32(const void* p) {
    uint32_t a;
    asm("{ .reg .u64 tmp; cvta.to.shared.u64 tmp, %1; cvt.u32.u64 %0, tmp; }"
        : "=r"(a) : "l"(p));
    return a;
}

// ---------------- warp MMA helpers (sm_80-era PTX, safe at compute_103) ----
__device__ __forceinline__ void ldsm_x4(uint32_t* r, uint32_t addr) {
    asm volatile("ldmatrix.sync.aligned.m8n8.x4.shared.b16 {%0,%1,%2,%3}, [%4];"
                 : "=r"(r[0]), "=r"(r[1]), "=r"(r[2]), "=r"(r[3]) : "r"(addr));
}
__device__ __forceinline__ void mma_bf16(float* c, const uint32_t* a,
                                         uint32_t b0, uint32_t b1) {
    asm volatile(
        "mma.sync.aligned.m16n8k16.row.col.f32.bf16.bf16.f32 "
        "{%0,%1,%2,%3}, {%4,%5,%6,%7}, {%8,%9}, {%0,%1,%2,%3};"
        : "+f"(c[0]), "+f"(c[1]), "+f"(c[2]), "+f"(c[3])
        : "r"(a[0]), "r"(a[1]), "r"(a[2]), "r"(a[3]), "r"(b0), "r"(b1));
}

// ---------------- SMEM layout (dynamic): per-warp buffers only ------------
// per-warp buffer (17920B):
//   GA: 32 rows x 144B (gather A+B fused; later h2-hi mma plane)
//   GB: 32 rows x 144B (h2-lo mma plane only)
//   GC: 32 rows x 272B (gather C; later nm staging rows x144)
#define W_GA 0
#define W_GB 4608
#define W_GC 9216
#define W_SIZE 17920
#define A_STRIDE 144
#define C_STRIDE 272
#define SM_TOTAL (4 * W_SIZE)    // 71680 bytes -> 3 CTAs/SM

// ================= precompute kernel: per-node projections =================
__global__ void __launch_bounds__(128) mpn_precompute_kernel(
    const float* __restrict__ x_node,
    const float* __restrict__ We1, const float* __restrict__ be1,
    const float* __restrict__ Wn1, const float* __restrict__ bn1)
{
    __shared__ __align__(16) float sW1[64 * 32];
    __shared__ __align__(16) float sWn[32 * 64];
    __shared__ __align__(16) float sbe1[32];
    __shared__ __align__(16) float sbn1[64];

    const int t = threadIdx.x;
    for (int i = t; i < 64 * 32; i += 128) sW1[i] = We1[i];
    for (int i = t; i < 32 * 64; i += 128) sWn[i] = Wn1[i];
    if (t < 32) sbe1[t] = be1[t];
    if (t < 64) sbn1[t] = bn1[t];
    __syncthreads();

    const int n = blockIdx.x * 128 + t;
    if (n >= N_NODES) return;

    float x[32];
    {
        const float4* px = reinterpret_cast<const float4*>(x_node + (size_t)n * 32);
#pragma unroll
        for (int i = 0; i < 8; i++) {
            float4 v = px[i];
            x[4*i] = v.x; x[4*i+1] = v.y; x[4*i+2] = v.z; x[4*i+3] = v.w;
        }
    }

    ull accA[16], accB[16], accC[32];
#pragma unroll
    for (int j = 0; j < 16; j++) {
        accA[j] = *reinterpret_cast<const ull*>(sbe1 + 2 * j);
        accB[j] = pack2(0.0f, 0.0f);
    }
#pragma unroll
    for (int j = 0; j < 32; j++)
        accC[j] = *reinterpret_cast<const ull*>(sbn1 + 2 * j);

#pragma unroll
    for (int i = 0; i < 32; i++) {
        ull ev = pack2(x[i], x[i]);
        const ulonglong2* wa = reinterpret_cast<const ulonglong2*>(sW1 + i * 32);
        const ulonglong2* wb = reinterpret_cast<const ulonglong2*>(sW1 + (32 + i) * 32);
        const ulonglong2* wc = reinterpret_cast<const ulonglong2*>(sWn + i * 64);
#pragma unroll
        for (int k = 0; k < 8; k++) {
            ulonglong2 w = wa[k];
            accA[2*k]   = fma2(ev, w.x, accA[2*k]);
            accA[2*k+1] = fma2(ev, w.y, accA[2*k+1]);
        }
#pragma unroll
        for (int k = 0; k < 8; k++) {
            ulonglong2 w = wb[k];
            accB[2*k]   = fma2(ev, w.x, accB[2*k]);
            accB[2*k+1] = fma2(ev, w.y, accB[2*k+1]);
        }
#pragma unroll
        for (int k = 0; k < 16; k++) {
            ulonglong2 w = wc[k];
            accC[2*k]   = fma2(ev, w.x, accC[2*k]);
            accC[2*k+1] = fma2(ev, w.y, accC[2*k+1]);
        }
    }

    ulonglong2* pA = reinterpret_cast<ulonglong2*>(g_A + (size_t)n * 32);
    ulonglong2* pB = reinterpret_cast<ulonglong2*>(g_B + (size_t)n * 32);
    ulonglong2* pC = reinterpret_cast<ulonglong2*>(g_C + (size_t)n * 64);
#pragma unroll
    for (int k = 0; k < 8; k++) pA[k] = make_ulonglong2(accA[2*k], accA[2*k+1]);
#pragma unroll
    for (int k = 0; k < 8; k++) pB[k] = make_ulonglong2(accB[2*k], accB[2*k+1]);
#pragma unroll
    for (int k = 0; k < 16; k++) pC[k] = make_ulonglong2(accC[2*k], accC[2*k+1]);
}

// ======= edge kernel: fused A+B gather, layer-4 warp mma.sync =====
__global__ void __launch_bounds__(128, 3) mpn_edge_kernel(
    const float* __restrict__ x_edge,
    const int* __restrict__ src, const int* __restrict__ dst,
    const float* __restrict__ Wn2,
    float* __restrict__ out_nm, float* __restrict__ out_em)
{
    extern __shared__ char smem[];
    const uint32_t smem_base = smem_u32(smem);
    const int t = threadIdx.x;
    const int wid = t >> 5;
    const int lane = t & 31;

    // ---- hoist Wn2 B-fragments (bf16 hi/lo) into registers, once ----
    const int col = lane >> 2;          // n within 8-col group
    const int krow = lane & 3;          // k-pair row within quad
    uint32_t Bh[4][4][2], Bl[4][4][2];
#pragma unroll
    for (int kt = 0; kt < 4; kt++) {
#pragma unroll
        for (int nt = 0; nt < 4; nt++) {
            int n = nt * 8 + col;
            int kp0 = kt * 8 + krow;
            int kp1 = kp0 + 4;
            float w00 = Wn2[(2 * kp0) * 32 + n];
            float w01 = Wn2[(2 * kp0 + 1) * 32 + n];
            float w10 = Wn2[(2 * kp1) * 32 + n];
            float w11 = Wn2[(2 * kp1 + 1) * 32 + n];
            uint32_t u00 = __float_as_uint(w00), u01 = __float_as_uint(w01);
            uint32_t u10 = __float_as_uint(w10), u11 = __float_as_uint(w11);
            Bh[kt][nt][0] = __byte_perm(u00, u01, 0x7632);
            Bh[kt][nt][1] = __byte_perm(u10, u11, 0x7632);
            float l00 = w00 - __uint_as_float(u00 & 0xFFFF0000u);
            float l01 = w01 - __uint_as_float(u01 & 0xFFFF0000u);
            float l10 = w10 - __uint_as_float(u10 & 0xFFFF0000u);
            float l11 = w11 - __uint_as_float(u11 & 0xFFFF0000u);
            uint32_t p0, p1;
            asm("cvt.rn.bf16x2.f32 %0, %1, %2;" : "=r"(p0) : "f"(l01), "f"(l00));
            asm("cvt.rn.bf16x2.f32 %0, %1, %2;" : "=r"(p1) : "f"(l11), "f"(l10));
            Bl[kt][nt][0] = p0;
            Bl[kt][nt][1] = p1;
        }
    }

    // epilogue bias pairs: cols nt*8 + krow*2, +1
    float2 bias[4];
#pragma unroll
    for (int nt = 0; nt < 4; nt++)
        bias[nt] = make_float2(c_bn2[nt * 8 + krow * 2], c_bn2[nt * 8 + krow * 2 + 1]);

    char* wbuf = smem + wid * W_SIZE;
    const uint32_t wbuf_u = smem_base + wid * W_SIZE;
    const uint32_t a_hi_base = wbuf_u + W_GA;
    const uint32_t a_lo_base = wbuf_u + W_GB;
    const uint32_t lds_lane_off = (uint32_t)(lane & 15) * A_STRIDE + (uint32_t)(lane >> 4) * 16;
    const int sub = lane >> 3;          // 0..3 : which edge within a gather instr
    const int qe  = lane & 7;           // 0..7 : 16B chunk within a 128B row

    for (int it = 0; it < NITER; it++) {
        const int e = (blockIdx.x * NITER + it) * 128 + wid * 32 + lane;
        const int s = src[e];
        const int d = dst[e];

        // ======== cooperative gathers into smem ========
        // A+B fused: the same lane fetches A[d] and B[s] chunks for the same
        // edge slot -> add during gather, store the sum once.
#pragma unroll
        for (int j = 0; j < 8; j++) {
            int eloc = 4 * j + sub;
            int dn = __shfl_sync(0xFFFFFFFFu, d, eloc);
            int sn = __shfl_sync(0xFFFFFFFFu, s, eloc);
            ulonglong2 va = *reinterpret_cast<const ulonglong2*>(g_A + (size_t)dn * 32 + qe * 4);
            ulonglong2 vb = *reinterpret_cast<const ulonglong2*>(g_B + (size_t)sn * 32 + qe * 4);
            ulonglong2 r;
            r.x = add2(va.x, vb.x);
            r.y = add2(va.y, vb.y);
            *reinterpret_cast<ulonglong2*>(wbuf + W_GA + eloc * A_STRIDE + qe * 16) = r;
        }
#pragma unroll
        for (int j = 0; j < 16; j++) {              // C rows (dst-indexed, 256B each)
            int c = 4 * j + sub;
            int eloc = c >> 1, half = c & 1;
            int dn = __shfl_sync(0xFFFFFFFFu, d, eloc);
            uint4 v = *reinterpret_cast<const uint4*>(g_C + (size_t)dn * 64 + half * 32 + qe * 4);
            *reinterpret_cast<uint4*>(wbuf + W_GC + eloc * C_STRIDE + half * 128 + qe * 16) = v;
        }
        __syncwarp();

        // ======== layer 1: acc1 = (A[d]+B[s]) + xe @ We1[64:70] ========
        ull acc1[16];
        {
            const ulonglong2* ra = reinterpret_cast<const ulonglong2*>(wbuf + W_GA + lane * A_STRIDE);
#pragma unroll
            for (int k = 0; k < 8; k++) {
                ulonglong2 a = ra[k];
                acc1[2*k]   = a.x;
                acc1[2*k+1] = a.y;
            }
        }
        float xe[6];
        {
            const float2* pe = reinterpret_cast<const float2*>(x_edge + (size_t)e * 6);
            float2 a = pe[0], b = pe[1], c = pe[2];
            xe[0]=a.x; xe[1]=a.y; xe[2]=b.x; xe[3]=b.y; xe[4]=c.x; xe[5]=c.y;
        }
#pragma unroll
        for (int i = 0; i < 6; i++) {
            ull ev = pack2(xe[i], xe[i]);
            const ulonglong2* w = reinterpret_cast<const ulonglong2*>(c_We1t + i * 32);
#pragma unroll
            for (int k = 0; k < 8; k++) {
                ulonglong2 wp = w[k];
                acc1[2*k]   = fma2(ev, wp.x, acc1[2*k]);
                acc1[2*k+1] = fma2(ev, wp.y, acc1[2*k+1]);
            }
        }
        float h1[32];
#pragma unroll
        for (int j = 0; j < 16; j++) relu2(acc1[j], h1[2*j], h1[2*j+1]);

        // ======== layer 2: em = relu(h1 @ We2 + be2), 6 accumulator chains ===
        ull acc2a[3], acc2b[3];
#pragma unroll
        for (int j = 0; j < 3; j++) {
            acc2a[j] = *reinterpret_cast<const ull*>(c_be2 + 2 * j);
            acc2b[j] = pack2(0.0f, 0.0f);
        }
#pragma unroll
        for (int i = 0; i < 16; i++) {
            const ull* wA = reinterpret_cast<const ull*>(c_We2 + i * 6);
            const ull* wB = reinterpret_cast<const ull*>(c_We2 + (16 + i) * 6);
            ull evA = pack2(h1[i], h1[i]);
            ull evB = pack2(h1[16 + i], h1[16 + i]);
            acc2a[0] = fma2(evA, wA[0], acc2a[0]);
            acc2a[1] = fma2(evA, wA[1], acc2a[1]);
            acc2a[2] = fma2(evA, wA[2], acc2a[2]);
            acc2b[0] = fma2(evB, wB[0], acc2b[0]);
            acc2b[1] = fma2(evB, wB[1], acc2b[1]);
            acc2b[2] = fma2(evB, wB[2], acc2b[2]);
        }
        float em[6];
#pragma unroll
        for (int j = 0; j < 3; j++) relu2(add2(acc2a[j], acc2b[j]), em[2*j], em[2*j+1]);
        {
            float2* po = reinterpret_cast<float2*>(out_em + (size_t)e * 6);
            po[0] = make_float2(em[0], em[1]);
            po[1] = make_float2(em[2], em[3]);
            po[2] = make_float2(em[4], em[5]);
        }

        // ======== layer 3: h2 = relu(C[d] + em @ Wn1[32:38]) ========
        // stream bf16 hi/lo planes straight to smem (own row only)
        ull emv[6];
#pragma unroll
        for (int i = 0; i < 6; i++) emv[i] = pack2(em[i], em[i]);

        const char* rowC = wbuf + W_GC + lane * C_STRIDE;
        char* rowH = wbuf + W_GA + lane * A_STRIDE;
        char* rowL = wbuf + W_GB + lane * A_STRIDE;
#pragma unroll
        for (int c = 0; c < 4; c++) {
            ull acc3[8];
            const longlong2* pc = reinterpret_cast<const longlong2*>(rowC + c * 64);
#pragma unroll
            for (int k = 0; k < 4; k++) {
                longlong2 v = pc[k];
                acc3[2*k] = (ull)v.x; acc3[2*k+1] = (ull)v.y;
            }
#pragma unroll
            for (int i = 0; i < 6; i++) {
                const ulonglong2* w = reinterpret_cast<const ulonglong2*>(c_Wn1t + i * 64 + c * 16);
#pragma unroll
                for (int k = 0; k < 4; k++) {
                    ulonglong2 wp = w[k];
                    acc3[2*k]   = fma2(emv[i], wp.x, acc3[2*k]);
                    acc3[2*k+1] = fma2(emv[i], wp.y, acc3[2*k+1]);
                }
            }
            uint32_t hi[8], lo[8];
#pragma unroll
            for (int j = 0; j < 8; j++) {
                float a, b;
                relu2(acc3[j], a, b);
                uint32_t ua = __float_as_uint(a);
                uint32_t ub = __float_as_uint(b);
                float la = a - __uint_as_float(ua & 0xFFFF0000u);
                float lb = b - __uint_as_float(ub & 0xFFFF0000u);
                hi[j] = __byte_perm(ua, ub, 0x7632);
                asm("cvt.rn.bf16x2.f32 %0, %1, %2;" : "=r"(lo[j]) : "f"(lb), "f"(la));
            }
            reinterpret_cast<uint4*>(rowH)[2*c]     = make_uint4(hi[0], hi[1], hi[2], hi[3]);
            reinterpret_cast<uint4*>(rowH)[2*c + 1] = make_uint4(hi[4], hi[5], hi[6], hi[7]);
            reinterpret_cast<uint4*>(rowL)[2*c]     = make_uint4(lo[0], lo[1], lo[2], lo[3]);
            reinterpret_cast<uint4*>(rowL)[2*c + 1] = make_uint4(lo[4], lo[5], lo[6], lo[7]);
        }
        __syncwarp();

        // ======== layer 4: C[32x32] = Ahi@(Bhi+Blo) + Alo@Bhi via mma.sync ===
        float acc[8][4];
#pragma unroll
        for (int f = 0; f < 8; f++) {
            acc[f][0] = 0.0f; acc[f][1] = 0.0f; acc[f][2] = 0.0f; acc[f][3] = 0.0f;
        }
#pragma unroll
        for (int kt = 0; kt < 4; kt++) {
            uint32_t a0[4], a1[4];
            ldsm_x4(a0, a_hi_base + lds_lane_off + kt * 32);
            ldsm_x4(a1, a_hi_base + lds_lane_off + 16 * A_STRIDE + kt * 32);
#pragma unroll
            for (int nt = 0; nt < 4; nt++) {
                mma_bf16(acc[nt],     a0, Bh[kt][nt][0], Bh[kt][nt][1]);
                mma_bf16(acc[nt],     a0, Bl[kt][nt][0], Bl[kt][nt][1]);
                mma_bf16(acc[4 + nt], a1, Bh[kt][nt][0], Bh[kt][nt][1]);
                mma_bf16(acc[4 + nt], a1, Bl[kt][nt][0], Bl[kt][nt][1]);
            }
        }
#pragma unroll
        for (int kt = 0; kt < 4; kt++) {
            uint32_t a0[4], a1[4];
            ldsm_x4(a0, a_lo_base + lds_lane_off + kt * 32);
            ldsm_x4(a1, a_lo_base + lds_lane_off + 16 * A_STRIDE + kt * 32);
#pragma unroll
            for (int nt = 0; nt < 4; nt++) {
                mma_bf16(acc[nt],     a0, Bh[kt][nt][0], Bh[kt][nt][1]);
                mma_bf16(acc[4 + nt], a1, Bh[kt][nt][0], Bh[kt][nt][1]);
            }
        }

        // ======== epilogue: bias+relu -> smem rows (overlay GC), coop scatter =
        const int r = lane >> 2;
        const int cb = krow * 2;
        char* nmbase = wbuf + W_GC;
#pragma unroll
        for (int mt = 0; mt < 2; mt++) {
#pragma unroll
            for (int nt = 0; nt < 4; nt++) {
                const float* a = acc[mt * 4 + nt];
                float v0 = fmaxf(a[0] + bias[nt].x, 0.0f);
                float v1 = fmaxf(a[1] + bias[nt].y, 0.0f);
                float v2 = fmaxf(a[2] + bias[nt].x, 0.0f);
                float v3 = fmaxf(a[3] + bias[nt].y, 0.0f);
                *reinterpret_cast<float2*>(nmbase + (mt * 16 + r) * A_STRIDE + (nt * 8 + cb) * 4)
                    = make_float2(v0, v1);
                *reinterpret_cast<float2*>(nmbase + (mt * 16 + r + 8) * A_STRIDE + (nt * 8 + cb) * 4)
                    = make_float2(v2, v3);
            }
        }
        __syncwarp();

#pragma unroll
        for (int j = 0; j < 8; j++) {
            int eloc = 4 * j + sub;
            int dn = __shfl_sync(0xFFFFFFFFu, d, eloc);
            float4 v = *reinterpret_cast<const float4*>(nmbase + eloc * A_STRIDE + qe * 16);
            asm volatile("red.global.add.v4.f32 [%0], {%1, %2, %3, %4};"
                         :: "l"(out_nm + (size_t)dn * 32 + qe * 4),
                            "f"(v.x), "f"(v.y), "f"(v.z), "f"(v.w) : "memory");
        }
        __syncwarp();   // nm smem reads done before next iter's C gather overwrites
    }
}

extern "C" void kernel_launch(void* const* d_in, const int* in_sizes, int n_in,
                              void* d_out, int out_size) {
    const float* x_node = (const float*)d_in[0];
    const float* x_edge = (const float*)d_in[1];
    const int*   src    = (const int*)d_in[2];
    const int*   dst    = (const int*)d_in[3];
    const float* We1    = (const float*)d_in[4];
    const float* be1    = (const float*)d_in[5];
    const float* We2    = (const float*)d_in[6];
    const float* be2    = (const float*)d_in[7];
    const float* Wn1    = (const float*)d_in[8];
    const float* bn1    = (const float*)d_in[9];
    const float* Wn2    = (const float*)d_in[10];
    const float* bn2    = (const float*)d_in[11];

    float* out    = (float*)d_out;
    float* out_nm = out;                        // [N_NODES, 32]
    float* out_em = out + (size_t)N_NODES * 32; // [N_EDGES, 6]

    cudaFuncSetAttribute(mpn_edge_kernel,
                         cudaFuncAttributeMaxDynamicSharedMemorySize, SM_TOTAL);

    // Stage small weights into constant memory (async D2D, graph-capturable).
    cudaMemcpyToSymbolAsync(c_We1t, We1 + 64 * 32, 6 * 32 * sizeof(float), 0,
                            cudaMemcpyDeviceToDevice);
    cudaMemcpyToSymbolAsync(c_We2, We2, 32 * 6 * sizeof(float), 0,
                            cudaMemcpyDeviceToDevice);
    cudaMemcpyToSymbolAsync(c_Wn1t, Wn1 + 32 * 64, 6 * 64 * sizeof(float), 0,
                            cudaMemcpyDeviceToDevice);
    cudaMemcpyToSymbolAsync(c_be2, be2, 6 * sizeof(float), 0,
                            cudaMemcpyDeviceToDevice);
    cudaMemcpyToSymbolAsync(c_bn2, bn2, 32 * sizeof(float), 0,
                            cudaMemcpyDeviceToDevice);

    cudaMemsetAsync(out_nm, 0, (size_t)N_NODES * 32 * sizeof(float));

    mpn_precompute_kernel<<<(N_NODES + 127) / 128, 128>>>(x_node, We1, be1, Wn1, bn1);

    mpn_edge_kernel<<<GRID_EDGE, 128, SM_TOTAL>>>(x_edge, src, dst, Wn2,
                                                  out_nm, out_em);
}

// round 13
// speedup vs baseline: 4.5010x; 1.1431x over previous
#include <cuda_runtime.h>
#include <cuda_bf16.h>
#include <cstddef>
#include <cstdint>

#define N_NODES 100000
#define N_EDGES 3200000
#define NITER 8                 // 128-edge tiles per block
#define GRID_EDGE 3125          // 3125 * 8 * 128 = 3,200,000

typedef unsigned long long ull;

// Per-node precomputed projections (static device scratch — allowed).
__device__ float g_A[(size_t)N_NODES * 32];  // be1 + x@We1[0:32,:]
__device__ float g_B[(size_t)N_NODES * 32];  // x@We1[32:64,:]
__device__ float g_C[(size_t)N_NODES * 64];  // bn1 + x@Wn1[0:32,:]

// Small weights in constant memory -> warp-uniform LDCU, zero L1 wavefronts.
__constant__ float c_We1t[6 * 32];   // We1 rows 64..69
__constant__ float c_We2[32 * 6];
__constant__ float c_Wn1t[6 * 64];   // Wn1 rows 32..37
__constant__ float c_be2[6];
__constant__ float c_bn2[32];

// ---------------- packed f32x2 helpers ----------------
__device__ __forceinline__ ull pack2(float a, float b) {
    ull r; asm("mov.b64 %0, {%1, %2};" : "=l"(r) : "f"(a), "f"(b)); return r;
}
__device__ __forceinline__ void unpack2(ull v, float& a, float& b) {
    asm("mov.b64 {%0, %1}, %2;" : "=f"(a), "=f"(b) : "l"(v));
}
__device__ __forceinline__ ull fma2(ull a, ull b, ull c) {
    ull d; asm("fma.rn.f32x2 %0, %1, %2, %3;" : "=l"(d) : "l"(a), "l"(b), "l"(c)); return d;
}
__device__ __forceinline__ ull add2(ull a, ull b) {
    ull d; asm("add.rn.f32x2 %0, %1, %2;" : "=l"(d) : "l"(a), "l"(b)); return d;
}
__device__ __forceinline__ void relu2(ull v, float& a, float& b) {
    unpack2(v, a, b);
    a = fmaxf(a, 0.0f);
    b = fmaxf(b, 0.0f);
}

__device__ __forceinline__ uint32_t smem_u32(const void* p) {
    uint32_t a;
    asm("{ .reg .u64 tmp; cvta.to.shared.u64 tmp, %1; cvt.u32.u64 %0, tmp; }"
        : "=r"(a) : "l"(p));
    return a;
}

// ---------------- cp.async helpers (sm_80 PTX, safe at compute_103) -------
__device__ __forceinline__ void cp_async16(uint32_t saddr, const void* gaddr) {
    asm volatile("cp.async.cg.shared.global [%0], [%1], 16;"
                 :: "r"(saddr), "l"(gaddr) : "memory");
}
__device__ __forceinline__ void cp_commit() {
    asm volatile("cp.async.commit_group;" ::: "memory");
}
__device__ __forceinline__ void cp_wait0() {
    asm volatile("cp.async.wait_group 0;" ::: "memory");
}

// ---------------- warp MMA helpers (sm_80-era PTX, safe at compute_103) ----
__device__ __forceinline__ void ldsm_x4(uint32_t* r, uint32_t addr) {
    asm volatile("ldmatrix.sync.aligned.m8n8.x4.shared.b16 {%0,%1,%2,%3}, [%4];"
                 : "=r"(r[0]), "=r"(r[1]), "=r"(r[2]), "=r"(r[3]) : "r"(addr));
}
__device__ __forceinline__ void mma_bf16(float* c, const uint32_t* a,
                                         uint32_t b0, uint32_t b1) {
    asm volatile(
        "mma.sync.aligned.m16n8k16.row.col.f32.bf16.bf16.f32 "
        "{%0,%1,%2,%3}, {%4,%5,%6,%7}, {%8,%9}, {%0,%1,%2,%3};"
        : "+f"(c[0]), "+f"(c[1]), "+f"(c[2]), "+f"(c[3])
        : "r"(a[0]), "r"(a[1]), "r"(a[2]), "r"(a[3]), "r"(b0), "r"(b1));
}

// ---------------- SMEM layout (dynamic): per-warp buffers only ------------
// per-warp buffer (17920B):
//   GA: 32 rows x 144B (gather A+B fused; later h2-hi mma plane)
//   GB: 32 rows x 144B (h2-lo mma plane only)
//   GC: 32 rows x 272B (cp.async C; later nm staging rows x144)
#define W_GA 0
#define W_GB 4608
#define W_GC 9216
#define W_SIZE 17920
#define A_STRIDE 144
#define C_STRIDE 272
#define SM_TOTAL (4 * W_SIZE)    // 71680 bytes -> 3 CTAs/SM

// ================= precompute kernel: per-node projections =================
__global__ void __launch_bounds__(128) mpn_precompute_kernel(
    const float* __restrict__ x_node,
    const float* __restrict__ We1, const float* __restrict__ be1,
    const float* __restrict__ Wn1, const float* __restrict__ bn1)
{
    __shared__ __align__(16) float sW1[64 * 32];
    __shared__ __align__(16) float sWn[32 * 64];
    __shared__ __align__(16) float sbe1[32];
    __shared__ __align__(16) float sbn1[64];

    const int t = threadIdx.x;
    for (int i = t; i < 64 * 32; i += 128) sW1[i] = We1[i];
    for (int i = t; i < 32 * 64; i += 128) sWn[i] = Wn1[i];
    if (t < 32) sbe1[t] = be1[t];
    if (t < 64) sbn1[t] = bn1[t];
    __syncthreads();

    const int n = blockIdx.x * 128 + t;
    if (n >= N_NODES) return;

    float x[32];
    {
        const float4* px = reinterpret_cast<const float4*>(x_node + (size_t)n * 32);
#pragma unroll
        for (int i = 0; i < 8; i++) {
            float4 v = px[i];
            x[4*i] = v.x; x[4*i+1] = v.y; x[4*i+2] = v.z; x[4*i+3] = v.w;
        }
    }

    ull accA[16], accB[16], accC[32];
#pragma unroll
    for (int j = 0; j < 16; j++) {
        accA[j] = *reinterpret_cast<const ull*>(sbe1 + 2 * j);
        accB[j] = pack2(0.0f, 0.0f);
    }
#pragma unroll
    for (int j = 0; j < 32; j++)
        accC[j] = *reinterpret_cast<const ull*>(sbn1 + 2 * j);

#pragma unroll
    for (int i = 0; i < 32; i++) {
        ull ev = pack2(x[i], x[i]);
        const ulonglong2* wa = reinterpret_cast<const ulonglong2*>(sW1 + i * 32);
        const ulonglong2* wb = reinterpret_cast<const ulonglong2*>(sW1 + (32 + i) * 32);
        const ulonglong2* wc = reinterpret_cast<const ulonglong2*>(sWn + i * 64);
#pragma unroll
        for (int k = 0; k < 8; k++) {
            ulonglong2 w = wa[k];
            accA[2*k]   = fma2(ev, w.x, accA[2*k]);
            accA[2*k+1] = fma2(ev, w.y, accA[2*k+1]);
        }
#pragma unroll
        for (int k = 0; k < 8; k++) {
            ulonglong2 w = wb[k];
            accB[2*k]   = fma2(ev, w.x, accB[2*k]);
            accB[2*k+1] = fma2(ev, w.y, accB[2*k+1]);
        }
#pragma unroll
        for (int k = 0; k < 16; k++) {
            ulonglong2 w = wc[k];
            accC[2*k]   = fma2(ev, w.x, accC[2*k]);
            accC[2*k+1] = fma2(ev, w.y, accC[2*k+1]);
        }
    }

    ulonglong2* pA = reinterpret_cast<ulonglong2*>(g_A + (size_t)n * 32);
    ulonglong2* pB = reinterpret_cast<ulonglong2*>(g_B + (size_t)n * 32);
    ulonglong2* pC = reinterpret_cast<ulonglong2*>(g_C + (size_t)n * 64);
#pragma unroll
    for (int k = 0; k < 8; k++) pA[k] = make_ulonglong2(accA[2*k], accA[2*k+1]);
#pragma unroll
    for (int k = 0; k < 8; k++) pB[k] = make_ulonglong2(accB[2*k], accB[2*k+1]);
#pragma unroll
    for (int k = 0; k < 16; k++) pC[k] = make_ulonglong2(accC[2*k], accC[2*k+1]);
}

// ======= edge kernel: async C gather, fused A+B, layer-4 warp mma.sync =====
__global__ void __launch_bounds__(128, 3) mpn_edge_kernel(
    const float* __restrict__ x_edge,
    const int* __restrict__ src, const int* __restrict__ dst,
    const float* __restrict__ Wn2,
    float* __restrict__ out_nm, float* __restrict__ out_em)
{
    extern __shared__ char smem[];
    const uint32_t smem_base = smem_u32(smem);
    const int t = threadIdx.x;
    const int wid = t >> 5;
    const int lane = t & 31;

    // ---- hoist Wn2 B-fragments (bf16 hi/lo) into registers, once ----
    const int col = lane >> 2;          // n within 8-col group
    const int krow = lane & 3;          // k-pair row within quad
    uint32_t Bh[4][4][2], Bl[4][4][2];
#pragma unroll
    for (int kt = 0; kt < 4; kt++) {
#pragma unroll
        for (int nt = 0; nt < 4; nt++) {
            int n = nt * 8 + col;
            int kp0 = kt * 8 + krow;
            int kp1 = kp0 + 4;
            float w00 = Wn2[(2 * kp0) * 32 + n];
            float w01 = Wn2[(2 * kp0 + 1) * 32 + n];
            float w10 = Wn2[(2 * kp1) * 32 + n];
            float w11 = Wn2[(2 * kp1 + 1) * 32 + n];
            uint32_t u00 = __float_as_uint(w00), u01 = __float_as_uint(w01);
            uint32_t u10 = __float_as_uint(w10), u11 = __float_as_uint(w11);
            Bh[kt][nt][0] = __byte_perm(u00, u01, 0x7632);
            Bh[kt][nt][1] = __byte_perm(u10, u11, 0x7632);
            float l00 = w00 - __uint_as_float(u00 & 0xFFFF0000u);
            float l01 = w01 - __uint_as_float(u01 & 0xFFFF0000u);
            float l10 = w10 - __uint_as_float(u10 & 0xFFFF0000u);
            float l11 = w11 - __uint_as_float(u11 & 0xFFFF0000u);
            uint32_t p0, p1;
            asm("cvt.rn.bf16x2.f32 %0, %1, %2;" : "=r"(p0) : "f"(l01), "f"(l00));
            asm("cvt.rn.bf16x2.f32 %0, %1, %2;" : "=r"(p1) : "f"(l11), "f"(l10));
            Bl[kt][nt][0] = p0;
            Bl[kt][nt][1] = p1;
        }
    }

    // epilogue bias pairs: cols nt*8 + krow*2, +1
    float2 bias[4];
#pragma unroll
    for (int nt = 0; nt < 4; nt++)
        bias[nt] = make_float2(c_bn2[nt * 8 + krow * 2], c_bn2[nt * 8 + krow * 2 + 1]);

    char* wbuf = smem + wid * W_SIZE;
    const uint32_t wbuf_u = smem_base + wid * W_SIZE;
    const uint32_t a_hi_base = wbuf_u + W_GA;
    const uint32_t a_lo_base = wbuf_u + W_GB;
    const uint32_t lds_lane_off = (uint32_t)(lane & 15) * A_STRIDE + (uint32_t)(lane >> 4) * 16;
    const int sub = lane >> 3;          // 0..3 : which edge within a gather instr
    const int qe  = lane & 7;           // 0..7 : 16B chunk within a 128B row

    const int e_base = blockIdx.x * NITER * 128 + wid * 32 + lane;
    int s_cur = src[e_base];
    int d_cur = dst[e_base];

    for (int it = 0; it < NITER; it++) {
        const int e = e_base + it * 128;
        const int s = s_cur;
        const int d = d_cur;

        // ======== C gather via cp.async (needed only at layer 3) ========
#pragma unroll
        for (int j = 0; j < 16; j++) {
            int c = 4 * j + sub;
            int eloc = c >> 1, half = c & 1;
            int dn = __shfl_sync(0xFFFFFFFFu, d, eloc);
            const float* gp = g_C + (size_t)dn * 64 + half * 32 + qe * 4;
            uint32_t sp = wbuf_u + W_GC + eloc * C_STRIDE + half * 128 + qe * 16;
            cp_async16(sp, gp);
        }
        cp_commit();

        // ======== A+B fused gather (consumed at layer 1) ========
#pragma unroll
        for (int j = 0; j < 8; j++) {
            int eloc = 4 * j + sub;
            int dn = __shfl_sync(0xFFFFFFFFu, d, eloc);
            int sn = __shfl_sync(0xFFFFFFFFu, s, eloc);
            ulonglong2 va = *reinterpret_cast<const ulonglong2*>(g_A + (size_t)dn * 32 + qe * 4);
            ulonglong2 vb = *reinterpret_cast<const ulonglong2*>(g_B + (size_t)sn * 32 + qe * 4);
            ulonglong2 r;
            r.x = add2(va.x, vb.x);
            r.y = add2(va.y, vb.y);
            *reinterpret_cast<ulonglong2*>(wbuf + W_GA + eloc * A_STRIDE + qe * 16) = r;
        }

        // xe load + next-iter index prefetch (latency off critical path)
        float xe[6];
        {
            const float2* pe = reinterpret_cast<const float2*>(x_edge + (size_t)e * 6);
            float2 a = pe[0], b = pe[1], c = pe[2];
            xe[0]=a.x; xe[1]=a.y; xe[2]=b.x; xe[3]=b.y; xe[4]=c.x; xe[5]=c.y;
        }
        int s_nxt = 0, d_nxt = 0;
        if (it + 1 < NITER) {
            s_nxt = src[e + 128];
            d_nxt = dst[e + 128];
        }
        __syncwarp();

        // ======== layer 1: acc1 = (A[d]+B[s]) + xe @ We1[64:70] ========
        ull acc1[16];
        {
            const ulonglong2* ra = reinterpret_cast<const ulonglong2*>(wbuf + W_GA + lane * A_STRIDE);
#pragma unroll
            for (int k = 0; k < 8; k++) {
                ulonglong2 a = ra[k];
                acc1[2*k]   = a.x;
                acc1[2*k+1] = a.y;
            }
        }
#pragma unroll
        for (int i = 0; i < 6; i++) {
            ull ev = pack2(xe[i], xe[i]);
            const ulonglong2* w = reinterpret_cast<const ulonglong2*>(c_We1t + i * 32);
#pragma unroll
            for (int k = 0; k < 8; k++) {
                ulonglong2 wp = w[k];
                acc1[2*k]   = fma2(ev, wp.x, acc1[2*k]);
                acc1[2*k+1] = fma2(ev, wp.y, acc1[2*k+1]);
            }
        }
        float h1[32];
#pragma unroll
        for (int j = 0; j < 16; j++) relu2(acc1[j], h1[2*j], h1[2*j+1]);

        // ======== layer 2: em = relu(h1 @ We2 + be2), 6 accumulator chains ===
        ull acc2a[3], acc2b[3];
#pragma unroll
        for (int j = 0; j < 3; j++) {
            acc2a[j] = *reinterpret_cast<const ull*>(c_be2 + 2 * j);
            acc2b[j] = pack2(0.0f, 0.0f);
        }
#pragma unroll
        for (int i = 0; i < 16; i++) {
            const ull* wA = reinterpret_cast<const ull*>(c_We2 + i * 6);
            const ull* wB = reinterpret_cast<const ull*>(c_We2 + (16 + i) * 6);
            ull evA = pack2(h1[i], h1[i]);
            ull evB = pack2(h1[16 + i], h1[16 + i]);
            acc2a[0] = fma2(evA, wA[0], acc2a[0]);
            acc2a[1] = fma2(evA, wA[1], acc2a[1]);
            acc2a[2] = fma2(evA, wA[2], acc2a[2]);
            acc2b[0] = fma2(evB, wB[0], acc2b[0]);
            acc2b[1] = fma2(evB, wB[1], acc2b[1]);
            acc2b[2] = fma2(evB, wB[2], acc2b[2]);
        }
        float em[6];
#pragma unroll
        for (int j = 0; j < 3; j++) relu2(add2(acc2a[j], acc2b[j]), em[2*j], em[2*j+1]);
        {
            float2* po = reinterpret_cast<float2*>(out_em + (size_t)e * 6);
            po[0] = make_float2(em[0], em[1]);
            po[1] = make_float2(em[2], em[3]);
            po[2] = make_float2(em[4], em[5]);
        }

        // ======== wait for async C, then layer 3 ========
        cp_wait0();
        __syncwarp();

        ull emv[6];
#pragma unroll
        for (int i = 0; i < 6; i++) emv[i] = pack2(em[i], em[i]);

        const char* rowC = wbuf + W_GC + lane * C_STRIDE;
        char* rowH = wbuf + W_GA + lane * A_STRIDE;
        char* rowL = wbuf + W_GB + lane * A_STRIDE;
#pragma unroll
        for (int c = 0; c < 4; c++) {
            ull acc3[8];
            const longlong2* pc = reinterpret_cast<const longlong2*>(rowC + c * 64);
#pragma unroll
            for (int k = 0; k < 4; k++) {
                longlong2 v = pc[k];
                acc3[2*k] = (ull)v.x; acc3[2*k+1] = (ull)v.y;
            }
#pragma unroll
            for (int i = 0; i < 6; i++) {
                const ulonglong2* w = reinterpret_cast<const ulonglong2*>(c_Wn1t + i * 64 + c * 16);
#pragma unroll
                for (int k = 0; k < 4; k++) {
                    ulonglong2 wp = w[k];
                    acc3[2*k]   = fma2(emv[i], wp.x, acc3[2*k]);
                    acc3[2*k+1] = fma2(emv[i], wp.y, acc3[2*k+1]);
                }
            }
            uint32_t hi[8], lo[8];
#pragma unroll
            for (int j = 0; j < 8; j++) {
                float a, b;
                relu2(acc3[j], a, b);
                uint32_t ua = __float_as_uint(a);
                uint32_t ub = __float_as_uint(b);
                float la = a - __uint_as_float(ua & 0xFFFF0000u);
                float lb = b - __uint_as_float(ub & 0xFFFF0000u);
                hi[j] = __byte_perm(ua, ub, 0x7632);
                asm("cvt.rn.bf16x2.f32 %0, %1, %2;" : "=r"(lo[j]) : "f"(lb), "f"(la));
            }
            reinterpret_cast<uint4*>(rowH)[2*c]     = make_uint4(hi[0], hi[1], hi[2], hi[3]);
            reinterpret_cast<uint4*>(rowH)[2*c + 1] = make_uint4(hi[4], hi[5], hi[6], hi[7]);
            reinterpret_cast<uint4*>(rowL)[2*c]     = make_uint4(lo[0], lo[1], lo[2], lo[3]);
            reinterpret_cast<uint4*>(rowL)[2*c + 1] = make_uint4(lo[4], lo[5], lo[6], lo[7]);
        }
        __syncwarp();

        // ======== layer 4: C[32x32] = Ahi@(Bhi+Blo) + Alo@Bhi via mma.sync ===
        float acc[8][4];
#pragma unroll
        for (int f = 0; f < 8; f++) {
            acc[f][0] = 0.0f; acc[f][1] = 0.0f; acc[f][2] = 0.0f; acc[f][3] = 0.0f;
        }
#pragma unroll
        for (int kt = 0; kt < 4; kt++) {
            uint32_t a0[4], a1[4];
            ldsm_x4(a0, a_hi_base + lds_lane_off + kt * 32);
            ldsm_x4(a1, a_hi_base + lds_lane_off + 16 * A_STRIDE + kt * 32);
#pragma unroll
            for (int nt = 0; nt < 4; nt++) {
                mma_bf16(acc[nt],     a0, Bh[kt][nt][0], Bh[kt][nt][1]);
                mma_bf16(acc[nt],     a0, Bl[kt][nt][0], Bl[kt][nt][1]);
                mma_bf16(acc[4 + nt], a1, Bh[kt][nt][0], Bh[kt][nt][1]);
                mma_bf16(acc[4 + nt], a1, Bl[kt][nt][0], Bl[kt][nt][1]);
            }
        }
#pragma unroll
        for (int kt = 0; kt < 4; kt++) {
            uint32_t a0[4], a1[4];
            ldsm_x4(a0, a_lo_base + lds_lane_off + kt * 32);
            ldsm_x4(a1, a_lo_base + lds_lane_off + 16 * A_STRIDE + kt * 32);
#pragma unroll
            for (int nt = 0; nt < 4; nt++) {
                mma_bf16(acc[nt],     a0, Bh[kt][nt][0], Bh[kt][nt][1]);
                mma_bf16(acc[4 + nt], a1, Bh[kt][nt][0], Bh[kt][nt][1]);
            }
        }

        // ======== epilogue: bias+relu -> smem rows (overlay GC), coop scatter =
        const int r = lane >> 2;
        const int cb = krow * 2;
        char* nmbase = wbuf + W_GC;
#pragma unroll
        for (int mt = 0; mt < 2; mt++) {
#pragma unroll
            for (int nt = 0; nt < 4; nt++) {
                const float* a = acc[mt * 4 + nt];
                float v0 = fmaxf(a[0] + bias[nt].x, 0.0f);
                float v1 = fmaxf(a[1] + bias[nt].y, 0.0f);
                float v2 = fmaxf(a[2] + bias[nt].x, 0.0f);
                float v3 = fmaxf(a[3] + bias[nt].y, 0.0f);
                *reinterpret_cast<float2*>(nmbase + (mt * 16 + r) * A_STRIDE + (nt * 8 + cb) * 4)
                    = make_float2(v0, v1);
                *reinterpret_cast<float2*>(nmbase + (mt * 16 + r + 8) * A_STRIDE + (nt * 8 + cb) * 4)
                    = make_float2(v2, v3);
            }
        }
        __syncwarp();

#pragma unroll
        for (int j = 0; j < 8; j++) {
            int eloc = 4 * j + sub;
            int dn = __shfl_sync(0xFFFFFFFFu, d, eloc);
            float4 v = *reinterpret_cast<const float4*>(nmbase + eloc * A_STRIDE + qe * 16);
            asm volatile("red.global.add.v4.f32 [%0], {%1, %2, %3, %4};"
                         :: "l"(out_nm + (size_t)dn * 32 + qe * 4),
                            "f"(v.x), "f"(v.y), "f"(v.z), "f"(v.w) : "memory");
        }
        __syncwarp();   // nm smem reads done before next iter's C cp.async lands

        s_cur = s_nxt;
        d_cur = d_nxt;
    }
}

extern "C" void kernel_launch(void* const* d_in, const int* in_sizes, int n_in,
                              void* d_out, int out_size) {
    const float* x_node = (const float*)d_in[0];
    const float* x_edge = (const float*)d_in[1];
    const int*   src    = (const int*)d_in[2];
    const int*   dst    = (const int*)d_in[3];
    const float* We1    = (const float*)d_in[4];
    const float* be1    = (const float*)d_in[5];
    const float* We2    = (const float*)d_in[6];
    const float* be2    = (const float*)d_in[7];
    const float* Wn1    = (const float*)d_in[8];
    const float* bn1    = (const float*)d_in[9];
    const float* Wn2    = (const float*)d_in[10];
    const float* bn2    = (const float*)d_in[11];

    float* out    = (float*)d_out;
    float* out_nm = out;                        // [N_NODES, 32]
    float* out_em = out + (size_t)N_NODES * 32; // [N_EDGES, 6]

    cudaFuncSetAttribute(mpn_edge_kernel,
                         cudaFuncAttributeMaxDynamicSharedMemorySize, SM_TOTAL);

    // Stage small weights into constant memory (async D2D, graph-capturable).
    cudaMemcpyToSymbolAsync(c_We1t, We1 + 64 * 32, 6 * 32 * sizeof(float), 0,
                            cudaMemcpyDeviceToDevice);
    cudaMemcpyToSymbolAsync(c_We2, We2, 32 * 6 * sizeof(float), 0,
                            cudaMemcpyDeviceToDevice);
    cudaMemcpyToSymbolAsync(c_Wn1t, Wn1 + 32 * 64, 6 * 64 * sizeof(float), 0,
                            cudaMemcpyDeviceToDevice);
    cudaMemcpyToSymbolAsync(c_be2, be2, 6 * sizeof(float), 0,
                            cudaMemcpyDeviceToDevice);
    cudaMemcpyToSymbolAsync(c_bn2, bn2, 32 * sizeof(float), 0,
                            cudaMemcpyDeviceToDevice);

    cudaMemsetAsync(out_nm, 0, (size_t)N_NODES * 32 * sizeof(float));

    mpn_precompute_kernel<<<(N_NODES + 127) / 128, 128>>>(x_node, We1, be1, Wn1, bn1);

    mpn_edge_kernel<<<GRID_EDGE, 128, SM_TOTAL>>>(x_edge, src, dst, Wn2,
                                                  out_nm, out_em);
}